// round 12
// baseline (speedup 1.0000x reference)
#include <cuda_runtime.h>
#include <cuda_fp16.h>
#include <cstdint>
#include <math.h>

// ---------------- model constants ----------------
#define C_DIM   1024
#define H_NUM   16
#define D_HEAD  64
#define L_NUM   8
#define T_SEQ   1024
#define B_SZ    2
#define M_ROWS  (B_SZ * T_SEQ)      // 2048
#define FF_DIM  4096
#define V_SZ    32000

// ---------------- device scratch ----------------
__device__ __align__(256) float  g_x   [M_ROWS * C_DIM];            // residual (fp32)
__device__ __align__(256) __half g_qkvh[M_ROWS * 3 * C_DIM];        // qkv (half)
__device__ __align__(256) __half g_hh  [M_ROWS * C_DIM];            // LN out / attn out
__device__ __align__(256) __half g_ffh [M_ROWS * FF_DIM];           // relu FF out
__device__ __align__(256) __half g_wph [L_NUM * 3 * C_DIM * C_DIM]; // qkv W [N,K] all layers
__device__ __align__(256) __half g_woh [L_NUM * C_DIM * C_DIM];     // Wo half [K,N]
__device__ __align__(256) __half g_w1h [L_NUM * C_DIM * FF_DIM];    // W1 half [K,N]
__device__ __align__(256) __half g_w2h [L_NUM * FF_DIM * C_DIM];    // W2 half [K,N]
__device__ __align__(256) __half g_tokh[V_SZ * C_DIM];              // tok [V,K]

// ============================================================
// helpers
// ============================================================
__device__ __forceinline__ uint32_t smem_u32(const void* p) {
    uint32_t a;
    asm("{ .reg .u64 t; cvta.to.shared.u64 t, %1; cvt.u32.u64 %0, t; }" : "=r"(a) : "l"(p));
    return a;
}
__device__ __forceinline__ void cpa16(uint32_t dst, const void* src) {
    asm volatile("cp.async.cg.shared.global [%0], [%1], 16;" :: "r"(dst), "l"(src));
}
__device__ __forceinline__ void ldsm4(uint32_t& r0, uint32_t& r1, uint32_t& r2, uint32_t& r3,
                                      uint32_t a) {
    asm volatile("ldmatrix.sync.aligned.m8n8.x4.shared.b16 {%0,%1,%2,%3}, [%4];"
        : "=r"(r0), "=r"(r1), "=r"(r2), "=r"(r3) : "r"(a));
}
__device__ __forceinline__ void ldsm4t(uint32_t& r0, uint32_t& r1, uint32_t& r2, uint32_t& r3,
                                       uint32_t a) {
    asm volatile("ldmatrix.sync.aligned.m8n8.x4.trans.shared.b16 {%0,%1,%2,%3}, [%4];"
        : "=r"(r0), "=r"(r1), "=r"(r2), "=r"(r3) : "r"(a));
}
__device__ __forceinline__ void mma_f16(float& c0, float& c1, float& c2, float& c3,
                                        uint32_t a0, uint32_t a1, uint32_t a2, uint32_t a3,
                                        uint32_t b0, uint32_t b1) {
    asm volatile("mma.sync.aligned.m16n8k16.row.col.f32.f16.f16.f32 "
        "{%0,%1,%2,%3}, {%4,%5,%6,%7}, {%8,%9}, {%0,%1,%2,%3};"
        : "+f"(c0), "+f"(c1), "+f"(c2), "+f"(c3)
        : "r"(a0), "r"(a1), "r"(a2), "r"(a3), "r"(b0), "r"(b1));
}

// ============================================================
// FP16 mma.sync GEMM: C[M,N] = A[M,K] @ B.  BK=64, 2-stage cp.async.
//   MT:  CTA M-tile (128 or 64); N-tile 128. 256 threads, 8 warps (2x4).
//   TRB=1: B stored [N,K] (A @ B^T), ldsm non-trans.
//   TRB=0: B stored [K,N] natural,  ldsm trans.
//   OUTH=1: half out (+bias)(+relu). OUTH=0: fp32 out (+bias)(+res).
// ============================================================
#define ROWH  72        // A / B-NK row pitch (64 + 8 pad halves)
#define ROWB  136       // B-KN row pitch (128 + 8 pad halves)

template<int MT, int OUTH, int TRB>
__global__ __launch_bounds__(256, MT == 64 ? 3 : 2)
void hgemm(const __half* __restrict__ A, const __half* __restrict__ B,
           void* __restrict__ Cout, const float* __restrict__ bias,
           const float* __restrict__ res, int N, int K, int relu)
{
    constexpr int MF      = MT / 32;                       // m-frags per warp
    constexpr int A_TILE  = MT * ROWH;                     // halves
    constexpr int B_TILE  = TRB ? 128 * ROWH : 64 * ROWB;  // halves
    constexpr int STAGE_B = (A_TILE + B_TILE) * 2;         // bytes

    extern __shared__ __half smh[];
    uint32_t sbase = smem_u32(smh);
    int tid  = threadIdx.x;
    int wid  = tid >> 5;
    int lane = tid & 31;
    int wm   = wid >> 2;          // 0..1
    int wn   = wid & 3;           // 0..3
    int bm = blockIdx.y * MT;
    int bn = blockIdx.x << 7;

    const __half* Ag = A + (size_t)bm * K;
    int NC = K >> 6;

    float acc[MF][4][4];
#pragma unroll
    for (int mf = 0; mf < MF; mf++)
#pragma unroll
        for (int nf = 0; nf < 4; nf++)
#pragma unroll
            for (int k = 0; k < 4; k++) acc[mf][nf][k] = 0.f;

    auto load_tile = [&](int ch, int stage) {
        int k0 = ch << 6;
        uint32_t so = sbase + (uint32_t)stage * STAGE_B;
        uint32_t bo = so + (uint32_t)A_TILE * 2u;
#pragma unroll
        for (int i = 0; i < MT / 32; i++) {                // A: MT rows x 64 k
            int id = tid + (i << 8);
            int r = id >> 3, c = (id & 7) << 3;
            cpa16(so + ((uint32_t)(r * ROWH + c) << 1), Ag + (size_t)r * K + k0 + c);
        }
        if (TRB) {                                         // B: 128 n-rows x 64 k
            const __half* Bg = B + (size_t)bn * K;
#pragma unroll
            for (int i = 0; i < 4; i++) {
                int id = tid + (i << 8);
                int r = id >> 3, c = (id & 7) << 3;
                cpa16(bo + ((uint32_t)(r * ROWH + c) << 1), Bg + (size_t)r * K + k0 + c);
            }
        } else {                                           // B: 64 k-rows x 128 n
#pragma unroll
            for (int i = 0; i < 4; i++) {
                int id = tid + (i << 8);
                int r = id >> 4, c = (id & 15) << 3;
                cpa16(bo + ((uint32_t)(r * ROWB + c) << 1),
                      B + (size_t)(k0 + r) * N + bn + c);
            }
        }
    };

    load_tile(0, 0);
    asm volatile("cp.async.commit_group;");

    uint32_t rA = (uint32_t)(wm * (MT / 2)) + (lane & 7) + (((lane >> 3) & 1) << 3);
    uint32_t kA = ((lane >> 4) & 1) << 3;
    uint32_t rB = (uint32_t)(wn << 5) + (lane & 7) + (((lane >> 4) & 1) << 3);
    uint32_t kB = ((lane >> 3) & 1) << 3;
    uint32_t rBt = (lane & 7) + (((lane >> 3) & 1) << 3);
    uint32_t cBt = (uint32_t)(wn << 5) + (((lane >> 4) & 1) << 3);

    for (int ch = 0; ch < NC; ch++) {
        if (ch > 0) __syncthreads();
        if (ch + 1 < NC) load_tile(ch + 1, (ch + 1) & 1);
        asm volatile("cp.async.commit_group;");
        asm volatile("cp.async.wait_group 1;");
        __syncthreads();

        uint32_t sA = sbase + (uint32_t)(ch & 1) * STAGE_B;
        uint32_t sB = sA + (uint32_t)A_TILE * 2u;
#pragma unroll
        for (int ks = 0; ks < 4; ks++) {
            uint32_t af[MF][4], bf[4][2];
            uint32_t kofs = (uint32_t)(ks << 4);
#pragma unroll
            for (int mf = 0; mf < MF; mf++) {
                uint32_t a = sA + (((rA + (uint32_t)(mf << 4)) * ROWH + kA + kofs) << 1);
                ldsm4(af[mf][0], af[mf][1], af[mf][2], af[mf][3], a);
            }
            if (TRB) {
#pragma unroll
                for (int p = 0; p < 2; p++) {
                    uint32_t a = sB + (((rB + (uint32_t)(p << 4)) * ROWH + kB + kofs) << 1);
                    ldsm4(bf[2 * p][0], bf[2 * p][1], bf[2 * p + 1][0], bf[2 * p + 1][1], a);
                }
            } else {
#pragma unroll
                for (int p = 0; p < 2; p++) {
                    uint32_t a = sB + (((kofs + rBt) * ROWB + cBt + (uint32_t)(p << 4)) << 1);
                    ldsm4t(bf[2 * p][0], bf[2 * p][1], bf[2 * p + 1][0], bf[2 * p + 1][1], a);
                }
            }
#pragma unroll
            for (int mf = 0; mf < MF; mf++)
#pragma unroll
                for (int nf = 0; nf < 4; nf++)
                    mma_f16(acc[mf][nf][0], acc[mf][nf][1], acc[mf][nf][2], acc[mf][nf][3],
                            af[mf][0], af[mf][1], af[mf][2], af[mf][3],
                            bf[nf][0], bf[nf][1]);
        }
    }

    // ---- epilogue ----
    int row0 = bm + wm * (MT / 2) + (lane >> 2);
    int col0 = bn + (wn << 5) + ((lane & 3) << 1);
#pragma unroll
    for (int mf = 0; mf < MF; mf++) {
#pragma unroll
        for (int half_ = 0; half_ < 2; half_++) {
            int row = row0 + (mf << 4) + half_ * 8;
#pragma unroll
            for (int nf = 0; nf < 4; nf++) {
                float vx = acc[mf][nf][half_ * 2 + 0];
                float vy = acc[mf][nf][half_ * 2 + 1];
                int c = (nf << 3);
                if (bias) {
                    vx += bias[col0 + c];
                    vy += bias[col0 + c + 1];
                }
                if (OUTH) {
                    if (relu) { vx = fmaxf(vx, 0.f); vy = fmaxf(vy, 0.f); }
                    __half2 hv = __floats2half2_rn(vx, vy);
                    *(__half2*)((__half*)Cout + (size_t)row * N + col0 + c) = hv;
                } else {
                    if (res) {
                        const float* rp = res + (size_t)row * N + col0 + c;
                        float2 r2 = *(const float2*)rp;
                        vx += r2.x; vy += r2.y;
                    }
                    float2 v; v.x = vx; v.y = vy;
                    *(float2*)((float*)Cout + (size_t)row * N + col0 + c) = v;
                }
            }
        }
    }
}

// ---------------- embedding ----------------
__global__ void k_embed(const int* __restrict__ idx,
                        const float* __restrict__ tok,
                        const float* __restrict__ pos,
                        float* __restrict__ x)
{
    int m = blockIdx.x;
    int c = threadIdx.x * 4;
    int t = m & (T_SEQ - 1);
    int v = idx[m];
    float4 a = *(const float4*)(tok + (size_t)v * C_DIM + c);
    float4 p = *(const float4*)(pos + (size_t)t * C_DIM + c);
    a.x += p.x; a.y += p.y; a.z += p.z; a.w += p.w;
    *(float4*)(x + (size_t)m * C_DIM + c) = a;
}

// ---------------- layernorm: fp32 in -> fp16 out ----------------
__global__ void k_ln(const float* __restrict__ x,
                     const float* __restrict__ sc,
                     const float* __restrict__ bi,
                     __half* __restrict__ out)
{
    int m = blockIdx.x;
    int tid = threadIdx.x;                 // 256 threads
    int c = tid * 4;
    float4 v = *(const float4*)(x + (size_t)m * C_DIM + c);
    float s = v.x + v.y + v.z + v.w;
    float q = v.x*v.x + v.y*v.y + v.z*v.z + v.w*v.w;

    __shared__ float rs[8], rq[8];
#pragma unroll
    for (int o = 16; o > 0; o >>= 1) {
        s += __shfl_xor_sync(0xffffffffu, s, o);
        q += __shfl_xor_sync(0xffffffffu, q, o);
    }
    if ((tid & 31) == 0) { rs[tid >> 5] = s; rq[tid >> 5] = q; }
    __syncthreads();
    float sum = 0.f, sq = 0.f;
#pragma unroll
    for (int w = 0; w < 8; w++) { sum += rs[w]; sq += rq[w]; }

    float mu = sum * (1.0f / C_DIM);
    float var = sq * (1.0f / C_DIM) - mu * mu;
    float rstd = rsqrtf(var + 1e-5f);

    float4 svv = *(const float4*)(sc + c);
    float4 bvv = *(const float4*)(bi + c);
    __half2 p0 = __floats2half2_rn((v.x - mu) * rstd * svv.x + bvv.x,
                                   (v.y - mu) * rstd * svv.y + bvv.y);
    __half2 p1 = __floats2half2_rn((v.z - mu) * rstd * svv.z + bvv.z,
                                   (v.w - mu) * rstd * svv.w + bvv.w);
    uint2 st;
    st.x = *(uint32_t*)&p0;
    st.y = *(uint32_t*)&p1;
    *(uint2*)(out + (size_t)m * C_DIM + c) = st;
}

// ---------------- pack qkv weights ALL layers -> [L][3C, C] half ----------------
__global__ __launch_bounds__(256)
void k_packQKV(const float* __restrict__ Wq, const float* __restrict__ Wk,
               const float* __restrict__ Wv, __half* __restrict__ out)
{
    __shared__ float t[32][65];
    int b  = blockIdx.x;
    int l  = b / 1536;
    b -= l * 1536;
    int kb = b & 31;
    int hh = (b >> 5) & 15;
    int s  = b >> 9;
    const float* W = (s == 0) ? Wq : ((s == 1) ? Wk : Wv);
    const float* Wb = W + ((size_t)l * H_NUM + hh) * C_DIM * D_HEAD + (size_t)(kb << 5) * D_HEAD;
    int tid = threadIdx.x;
#pragma unroll
    for (int i = 0; i < 8; i++) {
        int idx = tid + (i << 8);
        int r = idx >> 6, d = idx & 63;
        t[r][d] = Wb[(size_t)r * D_HEAD + d];
    }
    __syncthreads();
    __half* outl = out + (size_t)l * 3 * C_DIM * C_DIM;
    int n0 = s * 1024 + hh * 64;
#pragma unroll
    for (int i = 0; i < 8; i++) {
        int idx = tid + (i << 8);
        int d = idx >> 5, kk = idx & 31;
        outl[(size_t)(n0 + d) * C_DIM + (kb << 5) + kk] = __float2half_rn(t[kk][d]);
    }
}

// ---------------- pure fp32 -> fp16 convert (layout preserved) ----------------
__global__ __launch_bounds__(256)
void k_cvt(const float* __restrict__ in, __half* __restrict__ out)
{
    size_t i = ((size_t)blockIdx.x * 256 + threadIdx.x) * 8;
    float4 a = *(const float4*)(in + i);
    float4 b = *(const float4*)(in + i + 4);
    __half2 h0 = __floats2half2_rn(a.x, a.y);
    __half2 h1 = __floats2half2_rn(a.z, a.w);
    __half2 h2 = __floats2half2_rn(b.x, b.y);
    __half2 h3 = __floats2half2_rn(b.z, b.w);
    uint4 st;
    st.x = *(uint32_t*)&h0; st.y = *(uint32_t*)&h1;
    st.z = *(uint32_t*)&h2; st.w = *(uint32_t*)&h3;
    *(uint4*)(out + i) = st;
}

// ============================================================
// Tensor-core causal flash attention.
// ============================================================
#define AT_PAD  72
#define AT_TILEB (64 * AT_PAD * 2)

__global__ __launch_bounds__(128)
void k_attn(const __half* __restrict__ qkvh, __half* __restrict__ outb)
{
    __shared__ __half Qs[64][AT_PAD];
    __shared__ __half Ks[2][64][AT_PAD];
    __shared__ __half Vs[2][64][AT_PAD];

    int qt = blockIdx.x;
    int b  = blockIdx.y >> 4;
    int hh = blockIdx.y & 15;
    int tid = threadIdx.x;
    int wid = tid >> 5, lane = tid & 31;

    const __half* qp = qkvh + ((size_t)(b * T_SEQ + qt * 64)) * 3072 + hh * 64;
    const __half* kp = qkvh + ((size_t)(b * T_SEQ)) * 3072 + 1024 + hh * 64;
    const __half* vp = kp + 1024;

    uint32_t sQ = smem_u32(Qs);
    uint32_t sK = smem_u32(Ks);
    uint32_t sV = smem_u32(Vs);

#pragma unroll
    for (int i = 0; i < 4; i++) {
        int id = tid + (i << 7);
        int r = id >> 3, c = (id & 7) << 3;
        uint32_t off = (uint32_t)(r * AT_PAD + c) << 1;
        cpa16(sQ + off, qp + (size_t)r * 3072 + c);
        cpa16(sK + off, kp + (size_t)r * 3072 + c);
        cpa16(sV + off, vp + (size_t)r * 3072 + c);
    }
    asm volatile("cp.async.commit_group;");

    uint32_t qf[4][4];
    float oa[8][4];
    float m0 = -1e30f, m1 = -1e30f, l0 = 0.f, l1 = 0.f;
#pragma unroll
    for (int i = 0; i < 8; i++) { oa[i][0] = oa[i][1] = oa[i][2] = oa[i][3] = 0.f; }

    for (int kt = 0; kt <= qt; kt++) {
        if (kt > 0) __syncthreads();
        if (kt < qt) {
            uint32_t st = (uint32_t)((kt + 1) & 1) * AT_TILEB;
#pragma unroll
            for (int i = 0; i < 4; i++) {
                int id = tid + (i << 7);
                int r = id >> 3, c = (id & 7) << 3;
                uint32_t off = (uint32_t)(r * AT_PAD + c) << 1;
                cpa16(sK + st + off, kp + (size_t)((kt + 1) * 64 + r) * 3072 + c);
                cpa16(sV + st + off, vp + (size_t)((kt + 1) * 64 + r) * 3072 + c);
            }
        }
        asm volatile("cp.async.commit_group;");
        asm volatile("cp.async.wait_group 1;");
        __syncthreads();

        if (kt == 0) {
            uint32_t rAq = (uint32_t)(wid << 4) + (lane & 7) + (((lane >> 3) & 1) << 3);
#pragma unroll
            for (int kc = 0; kc < 4; kc++) {
                uint32_t kAq = (((lane >> 4) & 1) << 3) + (kc << 4);
                ldsm4(qf[kc][0], qf[kc][1], qf[kc][2], qf[kc][3],
                      sQ + ((rAq * AT_PAD + kAq) << 1));
            }
        }

        uint32_t sKt = sK + (uint32_t)(kt & 1) * AT_TILEB;
        uint32_t sVt = sV + (uint32_t)(kt & 1) * AT_TILEB;

        float s[8][4];
#pragma unroll
        for (int i = 0; i < 8; i++) { s[i][0] = s[i][1] = s[i][2] = s[i][3] = 0.f; }
        uint32_t rBk = (lane & 7) + (((lane >> 4) & 1) << 3);
        uint32_t kBo = ((lane >> 3) & 1) << 3;
#pragma unroll
        for (int kc = 0; kc < 4; kc++) {
#pragma unroll
            for (int p = 0; p < 4; p++) {
                uint32_t b0, b1, b2, b3;
                ldsm4(b0, b1, b2, b3,
                      sKt + (((rBk + (uint32_t)(p << 4)) * AT_PAD + kBo + (kc << 4)) << 1));
                mma_f16(s[2*p][0], s[2*p][1], s[2*p][2], s[2*p][3],
                        qf[kc][0], qf[kc][1], qf[kc][2], qf[kc][3], b0, b1);
                mma_f16(s[2*p+1][0], s[2*p+1][1], s[2*p+1][2], s[2*p+1][3],
                        qf[kc][0], qf[kc][1], qf[kc][2], qf[kc][3], b2, b3);
            }
        }
#pragma unroll
        for (int i = 0; i < 8; i++) {
            s[i][0] *= 0.125f; s[i][1] *= 0.125f; s[i][2] *= 0.125f; s[i][3] *= 0.125f;
        }
        if (kt == qt) {
            int r0 = (wid << 4) + (lane >> 2);
#pragma unroll
            for (int nf = 0; nf < 8; nf++) {
                int c0 = (nf << 3) + ((lane & 3) << 1);
                if (c0     > r0)     s[nf][0] = -1e30f;
                if (c0 + 1 > r0)     s[nf][1] = -1e30f;
                if (c0     > r0 + 8) s[nf][2] = -1e30f;
                if (c0 + 1 > r0 + 8) s[nf][3] = -1e30f;
            }
        }

        float mx0 = s[0][0], mx1 = s[0][2];
#pragma unroll
        for (int nf = 0; nf < 8; nf++) {
            mx0 = fmaxf(mx0, fmaxf(s[nf][0], s[nf][1]));
            mx1 = fmaxf(mx1, fmaxf(s[nf][2], s[nf][3]));
        }
        mx0 = fmaxf(mx0, __shfl_xor_sync(0xffffffffu, mx0, 1));
        mx0 = fmaxf(mx0, __shfl_xor_sync(0xffffffffu, mx0, 2));
        mx1 = fmaxf(mx1, __shfl_xor_sync(0xffffffffu, mx1, 1));
        mx1 = fmaxf(mx1, __shfl_xor_sync(0xffffffffu, mx1, 2));
        float mn0 = fmaxf(m0, mx0), mn1 = fmaxf(m1, mx1);
        float cr0 = __expf(m0 - mn0), cr1 = __expf(m1 - mn1);
        float rs0 = 0.f, rs1 = 0.f;
        uint32_t pa[4][4];
#pragma unroll
        for (int nf = 0; nf < 8; nf++) {
            float p0 = __expf(s[nf][0] - mn0);
            float p1 = __expf(s[nf][1] - mn0);
            float p2 = __expf(s[nf][2] - mn1);
            float p3 = __expf(s[nf][3] - mn1);
            rs0 += p0 + p1; rs1 += p2 + p3;
            __half2 h01 = __floats2half2_rn(p0, p1);
            __half2 h23 = __floats2half2_rn(p2, p3);
            int kc = nf >> 1, hi = (nf & 1) << 1;
            pa[kc][hi]     = *(uint32_t*)&h01;
            pa[kc][hi + 1] = *(uint32_t*)&h23;
        }
        rs0 += __shfl_xor_sync(0xffffffffu, rs0, 1);
        rs0 += __shfl_xor_sync(0xffffffffu, rs0, 2);
        rs1 += __shfl_xor_sync(0xffffffffu, rs1, 1);
        rs1 += __shfl_xor_sync(0xffffffffu, rs1, 2);
        l0 = l0 * cr0 + rs0; l1 = l1 * cr1 + rs1;
        m0 = mn0; m1 = mn1;
#pragma unroll
        for (int i = 0; i < 8; i++) {
            oa[i][0] *= cr0; oa[i][1] *= cr0; oa[i][2] *= cr1; oa[i][3] *= cr1;
        }

        uint32_t rV = (lane & 7) + (((lane >> 3) & 1) << 3);
        uint32_t cV = ((lane >> 4) & 1) << 3;
#pragma unroll
        for (int kc = 0; kc < 4; kc++) {
#pragma unroll
            for (int p = 0; p < 4; p++) {
                uint32_t b0, b1, b2, b3;
                ldsm4t(b0, b1, b2, b3,
                       sVt + ((((uint32_t)(kc << 4) + rV) * AT_PAD + (uint32_t)(p << 4) + cV) << 1));
                mma_f16(oa[2*p][0], oa[2*p][1], oa[2*p][2], oa[2*p][3],
                        pa[kc][0], pa[kc][1], pa[kc][2], pa[kc][3], b0, b1);
                mma_f16(oa[2*p+1][0], oa[2*p+1][1], oa[2*p+1][2], oa[2*p+1][3],
                        pa[kc][0], pa[kc][1], pa[kc][2], pa[kc][3], b2, b3);
            }
        }
    }

    float i0 = 1.0f / l0, i1 = 1.0f / l1;
    int r0 = qt * 64 + (wid << 4) + (lane >> 2);
    __half* ob = outb + (size_t)(b * T_SEQ) * C_DIM + hh * 64;
#pragma unroll
    for (int nf = 0; nf < 8; nf++) {
        int c = (nf << 3) + ((lane & 3) << 1);
        __half2 h0 = __floats2half2_rn(oa[nf][0] * i0, oa[nf][1] * i0);
        __half2 h1 = __floats2half2_rn(oa[nf][2] * i1, oa[nf][3] * i1);
        *(__half2*)(ob + (size_t)r0 * C_DIM + c)       = h0;
        *(__half2*)(ob + (size_t)(r0 + 8) * C_DIM + c) = h1;
    }
}

// ---------------- smem sizes per instantiation (BK=64, 2-stage) ----------------
#define GSM_128_NK  ((128 * ROWH + 128 * ROWH) * 2 * 2)   // 73728
#define GSM_64_NK   ((64 * ROWH + 128 * ROWH) * 2 * 2)    // 55296
#define GSM_128_KN  ((128 * ROWH + 64 * ROWB) * 2 * 2)    // 71680
#define GSM_64_KN   ((64 * ROWH + 64 * ROWB) * 2 * 2)     // 53248

// ---------------- launcher ----------------
extern "C" void kernel_launch(void* const* d_in, const int* in_sizes, int n_in,
                              void* d_out, int out_size)
{
    const int*   idx    = (const int*)  d_in[0];
    const float* tok    = (const float*)d_in[1];
    const float* pos    = (const float*)d_in[2];
    const float* ln1_s  = (const float*)d_in[3];
    const float* ln1_b  = (const float*)d_in[4];
    const float* Wq     = (const float*)d_in[5];
    const float* Wk     = (const float*)d_in[6];
    const float* Wv     = (const float*)d_in[7];
    const float* Wo     = (const float*)d_in[8];
    const float* bo     = (const float*)d_in[9];
    const float* ln2_s  = (const float*)d_in[10];
    const float* ln2_b  = (const float*)d_in[11];
    const float* W1     = (const float*)d_in[12];
    const float* b1     = (const float*)d_in[13];
    const float* W2     = (const float*)d_in[14];
    const float* b2     = (const float*)d_in[15];
    const float* lnf_s  = (const float*)d_in[16];
    const float* lnf_b  = (const float*)d_in[17];
    float* out = (float*)d_out;

    float *x;
    __half *qkvh, *hh, *ffh, *wph, *woh, *w1h, *w2h, *tokh;
    cudaGetSymbolAddress((void**)&x,     g_x);
    cudaGetSymbolAddress((void**)&qkvh,  g_qkvh);
    cudaGetSymbolAddress((void**)&hh,    g_hh);
    cudaGetSymbolAddress((void**)&ffh,   g_ffh);
    cudaGetSymbolAddress((void**)&wph,   g_wph);
    cudaGetSymbolAddress((void**)&woh,   g_woh);
    cudaGetSymbolAddress((void**)&w1h,   g_w1h);
    cudaGetSymbolAddress((void**)&w2h,   g_w2h);
    cudaGetSymbolAddress((void**)&tokh,  g_tokh);

    cudaFuncSetAttribute(hgemm<64,1,1>,  cudaFuncAttributeMaxDynamicSharedMemorySize, GSM_64_NK);
    cudaFuncSetAttribute(hgemm<128,0,1>, cudaFuncAttributeMaxDynamicSharedMemorySize, GSM_128_NK);
    cudaFuncSetAttribute(hgemm<64,1,0>,  cudaFuncAttributeMaxDynamicSharedMemorySize, GSM_64_KN);
    cudaFuncSetAttribute(hgemm<64,0,0>,  cudaFuncAttributeMaxDynamicSharedMemorySize, GSM_64_KN);

    // ---- one-time per call: weight conversion ----
    k_cvt<<<(V_SZ * C_DIM) / 2048, 256>>>(tok, tokh);
    k_cvt<<<(L_NUM * C_DIM * C_DIM) / 2048, 256>>>(Wo, woh);
    k_cvt<<<(L_NUM * C_DIM * FF_DIM) / 2048, 256>>>(W1, w1h);
    k_cvt<<<(L_NUM * FF_DIM * C_DIM) / 2048, 256>>>(W2, w2h);
    k_packQKV<<<L_NUM * 1536, 256>>>(Wq, Wk, Wv, wph);
    k_embed<<<M_ROWS, 256>>>(idx, tok, pos, x);

    for (int l = 0; l < L_NUM; l++) {
        // LN1 -> half
        k_ln<<<M_ROWS, 256>>>(x, ln1_s + l * C_DIM, ln1_b + l * C_DIM, hh);
        // qkv = hh @ wph^T -> half   (MT=64: 768 CTAs @ 3/SM)
        hgemm<64,1,1><<<dim3(3072 / 128, M_ROWS / 64), 256, GSM_64_NK>>>(
            hh, wph + (size_t)l * 3 * C_DIM * C_DIM, qkvh, nullptr, nullptr, 3072, C_DIM, 0);
        // tensor-core flash attention -> hh
        k_attn<<<dim3(T_SEQ / 64, B_SZ * H_NUM), 128>>>(qkvh, hh);
        // x = x + hh @ Wo + bo   (Wo [K,N], MT=64)
        hgemm<64,0,0><<<dim3(C_DIM / 128, M_ROWS / 64), 256, GSM_64_KN>>>(
            hh, woh + (size_t)l * C_DIM * C_DIM, x, bo + l * C_DIM, x, C_DIM, C_DIM, 0);
        // LN2 -> half
        k_ln<<<M_ROWS, 256>>>(x, ln2_s + l * C_DIM, ln2_b + l * C_DIM, hh);
        // ffh = relu(hh @ W1 + b1) -> half  (W1 [K,N], MT=64: 1024 CTAs @ 3/SM)
        hgemm<64,1,0><<<dim3(FF_DIM / 128, M_ROWS / 64), 256, GSM_64_KN>>>(
            hh, w1h + (size_t)l * C_DIM * FF_DIM, ffh, b1 + l * FF_DIM, nullptr, FF_DIM, C_DIM, 1);
        // x = x + ffh @ W2 + b2  (W2 [K,N], MT=64)
        hgemm<64,0,0><<<dim3(C_DIM / 128, M_ROWS / 64), 256, GSM_64_KN>>>(
            ffh, w2h + (size_t)l * FF_DIM * C_DIM, x, b2 + l * C_DIM, x, C_DIM, FF_DIM, 0);
    }

    // final LN + tied-embedding logits (tok [V,K] -> MT=128 TRB=1, many waves)
    k_ln<<<M_ROWS, 256>>>(x, lnf_s, lnf_b, hh);
    hgemm<128,0,1><<<dim3(V_SZ / 128, M_ROWS / 128), 256, GSM_128_NK>>>(
        hh, tokh, out, nullptr, nullptr, V_SZ, C_DIM, 0);
}

// round 13
// speedup vs baseline: 1.0018x; 1.0018x over previous
#include <cuda_runtime.h>
#include <cuda_fp16.h>
#include <cstdint>
#include <math.h>

// ---------------- model constants ----------------
#define C_DIM   1024
#define H_NUM   16
#define D_HEAD  64
#define L_NUM   8
#define T_SEQ   1024
#define B_SZ    2
#define M_ROWS  (B_SZ * T_SEQ)      // 2048
#define FF_DIM  4096
#define V_SZ    32000

// ---------------- device scratch ----------------
__device__ __align__(256) float  g_x   [M_ROWS * C_DIM];            // residual (fp32)
__device__ __align__(256) __half g_qkvh[M_ROWS * 3 * C_DIM];        // qkv (half)
__device__ __align__(256) __half g_hh  [M_ROWS * C_DIM];            // LN out / attn out
__device__ __align__(256) __half g_ffh [M_ROWS * FF_DIM];           // relu FF out
__device__ __align__(256) __half g_wph [L_NUM * 3 * C_DIM * C_DIM]; // qkv W [N,K] all layers
__device__ __align__(256) __half g_woh [L_NUM * C_DIM * C_DIM];     // Wo half [K,N]
__device__ __align__(256) __half g_w1h [L_NUM * C_DIM * FF_DIM];    // W1 half [K,N]
__device__ __align__(256) __half g_w2h [L_NUM * FF_DIM * C_DIM];    // W2 half [K,N]
__device__ __align__(256) __half g_tokh[V_SZ * C_DIM];              // tok [V,K]

// ============================================================
// helpers
// ============================================================
__device__ __forceinline__ uint32_t smem_u32(const void* p) {
    uint32_t a;
    asm("{ .reg .u64 t; cvta.to.shared.u64 t, %1; cvt.u32.u64 %0, t; }" : "=r"(a) : "l"(p));
    return a;
}
__device__ __forceinline__ void cpa16(uint32_t dst, const void* src) {
    asm volatile("cp.async.cg.shared.global [%0], [%1], 16;" :: "r"(dst), "l"(src));
}
__device__ __forceinline__ void ldsm4(uint32_t& r0, uint32_t& r1, uint32_t& r2, uint32_t& r3,
                                      uint32_t a) {
    asm volatile("ldmatrix.sync.aligned.m8n8.x4.shared.b16 {%0,%1,%2,%3}, [%4];"
        : "=r"(r0), "=r"(r1), "=r"(r2), "=r"(r3) : "r"(a));
}
__device__ __forceinline__ void ldsm4t(uint32_t& r0, uint32_t& r1, uint32_t& r2, uint32_t& r3,
                                       uint32_t a) {
    asm volatile("ldmatrix.sync.aligned.m8n8.x4.trans.shared.b16 {%0,%1,%2,%3}, [%4];"
        : "=r"(r0), "=r"(r1), "=r"(r2), "=r"(r3) : "r"(a));
}
__device__ __forceinline__ void mma_f16(float& c0, float& c1, float& c2, float& c3,
                                        uint32_t a0, uint32_t a1, uint32_t a2, uint32_t a3,
                                        uint32_t b0, uint32_t b1) {
    asm volatile("mma.sync.aligned.m16n8k16.row.col.f32.f16.f16.f32 "
        "{%0,%1,%2,%3}, {%4,%5,%6,%7}, {%8,%9}, {%0,%1,%2,%3};"
        : "+f"(c0), "+f"(c1), "+f"(c2), "+f"(c3)
        : "r"(a0), "r"(a1), "r"(a2), "r"(a3), "r"(b0), "r"(b1));
}

// ============================================================
// FP16 mma.sync GEMM: C[M,N] = A[M,K] @ B.  BK=64, 2-stage cp.async.
//   MT:  CTA M-tile (128 or 64); N-tile 128. 256 threads, 8 warps (2x4).
//   TRB=1: B stored [N,K] (A @ B^T), ldsm non-trans.
//   TRB=0: B stored [K,N] natural,  ldsm trans.
//   OUTH=1: half out (+bias)(+relu). OUTH=0: fp32 out (+bias)(+res).
// ============================================================
#define ROWH  72        // A / B-NK row pitch (64 + 8 pad halves)
#define ROWB  136       // B-KN row pitch (128 + 8 pad halves)

template<int MT, int OUTH, int TRB>
__global__ __launch_bounds__(256, MT == 64 ? 3 : 2)
void hgemm(const __half* __restrict__ A, const __half* __restrict__ B,
           void* __restrict__ Cout, const float* __restrict__ bias,
           const float* __restrict__ res, int N, int K, int relu)
{
    constexpr int MF      = MT / 32;                       // m-frags per warp
    constexpr int A_TILE  = MT * ROWH;                     // halves
    constexpr int B_TILE  = TRB ? 128 * ROWH : 64 * ROWB;  // halves
    constexpr int STAGE_B = (A_TILE + B_TILE) * 2;         // bytes

    extern __shared__ __half smh[];
    uint32_t sbase = smem_u32(smh);
    int tid  = threadIdx.x;
    int wid  = tid >> 5;
    int lane = tid & 31;
    int wm   = wid >> 2;          // 0..1
    int wn   = wid & 3;           // 0..3
    int bm = blockIdx.y * MT;
    int bn = blockIdx.x << 7;

    const __half* Ag = A + (size_t)bm * K;
    int NC = K >> 6;

    float acc[MF][4][4];
#pragma unroll
    for (int mf = 0; mf < MF; mf++)
#pragma unroll
        for (int nf = 0; nf < 4; nf++)
#pragma unroll
            for (int k = 0; k < 4; k++) acc[mf][nf][k] = 0.f;

    auto load_tile = [&](int ch, int stage) {
        int k0 = ch << 6;
        uint32_t so = sbase + (uint32_t)stage * STAGE_B;
        uint32_t bo = so + (uint32_t)A_TILE * 2u;
#pragma unroll
        for (int i = 0; i < MT / 32; i++) {                // A: MT rows x 64 k
            int id = tid + (i << 8);
            int r = id >> 3, c = (id & 7) << 3;
            cpa16(so + ((uint32_t)(r * ROWH + c) << 1), Ag + (size_t)r * K + k0 + c);
        }
        if (TRB) {                                         // B: 128 n-rows x 64 k
            const __half* Bg = B + (size_t)bn * K;
#pragma unroll
            for (int i = 0; i < 4; i++) {
                int id = tid + (i << 8);
                int r = id >> 3, c = (id & 7) << 3;
                cpa16(bo + ((uint32_t)(r * ROWH + c) << 1), Bg + (size_t)r * K + k0 + c);
            }
        } else {                                           // B: 64 k-rows x 128 n
#pragma unroll
            for (int i = 0; i < 4; i++) {
                int id = tid + (i << 8);
                int r = id >> 4, c = (id & 15) << 3;
                cpa16(bo + ((uint32_t)(r * ROWB + c) << 1),
                      B + (size_t)(k0 + r) * N + bn + c);
            }
        }
    };

    load_tile(0, 0);
    asm volatile("cp.async.commit_group;");

    uint32_t rA = (uint32_t)(wm * (MT / 2)) + (lane & 7) + (((lane >> 3) & 1) << 3);
    uint32_t kA = ((lane >> 4) & 1) << 3;
    uint32_t rB = (uint32_t)(wn << 5) + (lane & 7) + (((lane >> 4) & 1) << 3);
    uint32_t kB = ((lane >> 3) & 1) << 3;
    uint32_t rBt = (lane & 7) + (((lane >> 3) & 1) << 3);
    uint32_t cBt = (uint32_t)(wn << 5) + (((lane >> 4) & 1) << 3);

    for (int ch = 0; ch < NC; ch++) {
        if (ch > 0) __syncthreads();
        if (ch + 1 < NC) load_tile(ch + 1, (ch + 1) & 1);
        asm volatile("cp.async.commit_group;");
        asm volatile("cp.async.wait_group 1;");
        __syncthreads();

        uint32_t sA = sbase + (uint32_t)(ch & 1) * STAGE_B;
        uint32_t sB = sA + (uint32_t)A_TILE * 2u;
#pragma unroll
        for (int ks = 0; ks < 4; ks++) {
            uint32_t af[MF][4], bf[4][2];
            uint32_t kofs = (uint32_t)(ks << 4);
#pragma unroll
            for (int mf = 0; mf < MF; mf++) {
                uint32_t a = sA + (((rA + (uint32_t)(mf << 4)) * ROWH + kA + kofs) << 1);
                ldsm4(af[mf][0], af[mf][1], af[mf][2], af[mf][3], a);
            }
            if (TRB) {
#pragma unroll
                for (int p = 0; p < 2; p++) {
                    uint32_t a = sB + (((rB + (uint32_t)(p << 4)) * ROWH + kB + kofs) << 1);
                    ldsm4(bf[2 * p][0], bf[2 * p][1], bf[2 * p + 1][0], bf[2 * p + 1][1], a);
                }
            } else {
#pragma unroll
                for (int p = 0; p < 2; p++) {
                    uint32_t a = sB + (((kofs + rBt) * ROWB + cBt + (uint32_t)(p << 4)) << 1);
                    ldsm4t(bf[2 * p][0], bf[2 * p][1], bf[2 * p + 1][0], bf[2 * p + 1][1], a);
                }
            }
#pragma unroll
            for (int mf = 0; mf < MF; mf++)
#pragma unroll
                for (int nf = 0; nf < 4; nf++)
                    mma_f16(acc[mf][nf][0], acc[mf][nf][1], acc[mf][nf][2], acc[mf][nf][3],
                            af[mf][0], af[mf][1], af[mf][2], af[mf][3],
                            bf[nf][0], bf[nf][1]);
        }
    }

    // ---- epilogue ----
    int row0 = bm + wm * (MT / 2) + (lane >> 2);
    int col0 = bn + (wn << 5) + ((lane & 3) << 1);
#pragma unroll
    for (int mf = 0; mf < MF; mf++) {
#pragma unroll
        for (int half_ = 0; half_ < 2; half_++) {
            int row = row0 + (mf << 4) + half_ * 8;
#pragma unroll
            for (int nf = 0; nf < 4; nf++) {
                float vx = acc[mf][nf][half_ * 2 + 0];
                float vy = acc[mf][nf][half_ * 2 + 1];
                int c = (nf << 3);
                if (bias) {
                    vx += bias[col0 + c];
                    vy += bias[col0 + c + 1];
                }
                if (OUTH) {
                    if (relu) { vx = fmaxf(vx, 0.f); vy = fmaxf(vy, 0.f); }
                    __half2 hv = __floats2half2_rn(vx, vy);
                    *(__half2*)((__half*)Cout + (size_t)row * N + col0 + c) = hv;
                } else {
                    if (res) {
                        const float* rp = res + (size_t)row * N + col0 + c;
                        float2 r2 = *(const float2*)rp;
                        vx += r2.x; vy += r2.y;
                    }
                    float2 v; v.x = vx; v.y = vy;
                    *(float2*)((float*)Cout + (size_t)row * N + col0 + c) = v;
                }
            }
        }
    }
}

// ---------------- embedding ----------------
__global__ void k_embed(const int* __restrict__ idx,
                        const float* __restrict__ tok,
                        const float* __restrict__ pos,
                        float* __restrict__ x)
{
    int m = blockIdx.x;
    int c = threadIdx.x * 4;
    int t = m & (T_SEQ - 1);
    int v = idx[m];
    float4 a = *(const float4*)(tok + (size_t)v * C_DIM + c);
    float4 p = *(const float4*)(pos + (size_t)t * C_DIM + c);
    a.x += p.x; a.y += p.y; a.z += p.z; a.w += p.w;
    *(float4*)(x + (size_t)m * C_DIM + c) = a;
}

// ---------------- layernorm: fp32 in -> fp16 out ----------------
__global__ void k_ln(const float* __restrict__ x,
                     const float* __restrict__ sc,
                     const float* __restrict__ bi,
                     __half* __restrict__ out)
{
    int m = blockIdx.x;
    int tid = threadIdx.x;                 // 256 threads
    int c = tid * 4;
    float4 v = *(const float4*)(x + (size_t)m * C_DIM + c);
    float s = v.x + v.y + v.z + v.w;
    float q = v.x*v.x + v.y*v.y + v.z*v.z + v.w*v.w;

    __shared__ float rs[8], rq[8];
#pragma unroll
    for (int o = 16; o > 0; o >>= 1) {
        s += __shfl_xor_sync(0xffffffffu, s, o);
        q += __shfl_xor_sync(0xffffffffu, q, o);
    }
    if ((tid & 31) == 0) { rs[tid >> 5] = s; rq[tid >> 5] = q; }
    __syncthreads();
    float sum = 0.f, sq = 0.f;
#pragma unroll
    for (int w = 0; w < 8; w++) { sum += rs[w]; sq += rq[w]; }

    float mu = sum * (1.0f / C_DIM);
    float var = sq * (1.0f / C_DIM) - mu * mu;
    float rstd = rsqrtf(var + 1e-5f);

    float4 svv = *(const float4*)(sc + c);
    float4 bvv = *(const float4*)(bi + c);
    __half2 p0 = __floats2half2_rn((v.x - mu) * rstd * svv.x + bvv.x,
                                   (v.y - mu) * rstd * svv.y + bvv.y);
    __half2 p1 = __floats2half2_rn((v.z - mu) * rstd * svv.z + bvv.z,
                                   (v.w - mu) * rstd * svv.w + bvv.w);
    uint2 st;
    st.x = *(uint32_t*)&p0;
    st.y = *(uint32_t*)&p1;
    *(uint2*)(out + (size_t)m * C_DIM + c) = st;
}

// ---------------- pack qkv weights ALL layers -> [L][3C, C] half ----------------
__global__ __launch_bounds__(256)
void k_packQKV(const float* __restrict__ Wq, const float* __restrict__ Wk,
               const float* __restrict__ Wv, __half* __restrict__ out)
{
    __shared__ float t[32][65];
    int b  = blockIdx.x;
    int l  = b / 1536;
    b -= l * 1536;
    int kb = b & 31;
    int hh = (b >> 5) & 15;
    int s  = b >> 9;
    const float* W = (s == 0) ? Wq : ((s == 1) ? Wk : Wv);
    const float* Wb = W + ((size_t)l * H_NUM + hh) * C_DIM * D_HEAD + (size_t)(kb << 5) * D_HEAD;
    int tid = threadIdx.x;
#pragma unroll
    for (int i = 0; i < 8; i++) {
        int idx = tid + (i << 8);
        int r = idx >> 6, d = idx & 63;
        t[r][d] = Wb[(size_t)r * D_HEAD + d];
    }
    __syncthreads();
    __half* outl = out + (size_t)l * 3 * C_DIM * C_DIM;
    int n0 = s * 1024 + hh * 64;
#pragma unroll
    for (int i = 0; i < 8; i++) {
        int idx = tid + (i << 8);
        int d = idx >> 5, kk = idx & 31;
        outl[(size_t)(n0 + d) * C_DIM + (kb << 5) + kk] = __float2half_rn(t[kk][d]);
    }
}

// ---------------- pure fp32 -> fp16 convert (layout preserved) ----------------
__global__ __launch_bounds__(256)
void k_cvt(const float* __restrict__ in, __half* __restrict__ out)
{
    size_t i = ((size_t)blockIdx.x * 256 + threadIdx.x) * 8;
    float4 a = *(const float4*)(in + i);
    float4 b = *(const float4*)(in + i + 4);
    __half2 h0 = __floats2half2_rn(a.x, a.y);
    __half2 h1 = __floats2half2_rn(a.z, a.w);
    __half2 h2 = __floats2half2_rn(b.x, b.y);
    __half2 h3 = __floats2half2_rn(b.z, b.w);
    uint4 st;
    st.x = *(uint32_t*)&h0; st.y = *(uint32_t*)&h1;
    st.z = *(uint32_t*)&h2; st.w = *(uint32_t*)&h3;
    *(uint4*)(out + i) = st;
}

// ============================================================
// Tensor-core causal flash attention.
// ============================================================
#define AT_PAD  72
#define AT_TILEB (64 * AT_PAD * 2)

__global__ __launch_bounds__(128)
void k_attn(const __half* __restrict__ qkvh, __half* __restrict__ outb)
{
    __shared__ __half Qs[64][AT_PAD];
    __shared__ __half Ks[2][64][AT_PAD];
    __shared__ __half Vs[2][64][AT_PAD];

    int qt = blockIdx.x;
    int b  = blockIdx.y >> 4;
    int hh = blockIdx.y & 15;
    int tid = threadIdx.x;
    int wid = tid >> 5, lane = tid & 31;

    const __half* qp = qkvh + ((size_t)(b * T_SEQ + qt * 64)) * 3072 + hh * 64;
    const __half* kp = qkvh + ((size_t)(b * T_SEQ)) * 3072 + 1024 + hh * 64;
    const __half* vp = kp + 1024;

    uint32_t sQ = smem_u32(Qs);
    uint32_t sK = smem_u32(Ks);
    uint32_t sV = smem_u32(Vs);

#pragma unroll
    for (int i = 0; i < 4; i++) {
        int id = tid + (i << 7);
        int r = id >> 3, c = (id & 7) << 3;
        uint32_t off = (uint32_t)(r * AT_PAD + c) << 1;
        cpa16(sQ + off, qp + (size_t)r * 3072 + c);
        cpa16(sK + off, kp + (size_t)r * 3072 + c);
        cpa16(sV + off, vp + (size_t)r * 3072 + c);
    }
    asm volatile("cp.async.commit_group;");

    uint32_t qf[4][4];
    float oa[8][4];
    float m0 = -1e30f, m1 = -1e30f, l0 = 0.f, l1 = 0.f;
#pragma unroll
    for (int i = 0; i < 8; i++) { oa[i][0] = oa[i][1] = oa[i][2] = oa[i][3] = 0.f; }

    for (int kt = 0; kt <= qt; kt++) {
        if (kt > 0) __syncthreads();
        if (kt < qt) {
            uint32_t st = (uint32_t)((kt + 1) & 1) * AT_TILEB;
#pragma unroll
            for (int i = 0; i < 4; i++) {
                int id = tid + (i << 7);
                int r = id >> 3, c = (id & 7) << 3;
                uint32_t off = (uint32_t)(r * AT_PAD + c) << 1;
                cpa16(sK + st + off, kp + (size_t)((kt + 1) * 64 + r) * 3072 + c);
                cpa16(sV + st + off, vp + (size_t)((kt + 1) * 64 + r) * 3072 + c);
            }
        }
        asm volatile("cp.async.commit_group;");
        asm volatile("cp.async.wait_group 1;");
        __syncthreads();

        if (kt == 0) {
            uint32_t rAq = (uint32_t)(wid << 4) + (lane & 7) + (((lane >> 3) & 1) << 3);
#pragma unroll
            for (int kc = 0; kc < 4; kc++) {
                uint32_t kAq = (((lane >> 4) & 1) << 3) + (kc << 4);
                ldsm4(qf[kc][0], qf[kc][1], qf[kc][2], qf[kc][3],
                      sQ + ((rAq * AT_PAD + kAq) << 1));
            }
        }

        uint32_t sKt = sK + (uint32_t)(kt & 1) * AT_TILEB;
        uint32_t sVt = sV + (uint32_t)(kt & 1) * AT_TILEB;

        float s[8][4];
#pragma unroll
        for (int i = 0; i < 8; i++) { s[i][0] = s[i][1] = s[i][2] = s[i][3] = 0.f; }
        uint32_t rBk = (lane & 7) + (((lane >> 4) & 1) << 3);
        uint32_t kBo = ((lane >> 3) & 1) << 3;
#pragma unroll
        for (int kc = 0; kc < 4; kc++) {
#pragma unroll
            for (int p = 0; p < 4; p++) {
                uint32_t b0, b1, b2, b3;
                ldsm4(b0, b1, b2, b3,
                      sKt + (((rBk + (uint32_t)(p << 4)) * AT_PAD + kBo + (kc << 4)) << 1));
                mma_f16(s[2*p][0], s[2*p][1], s[2*p][2], s[2*p][3],
                        qf[kc][0], qf[kc][1], qf[kc][2], qf[kc][3], b0, b1);
                mma_f16(s[2*p+1][0], s[2*p+1][1], s[2*p+1][2], s[2*p+1][3],
                        qf[kc][0], qf[kc][1], qf[kc][2], qf[kc][3], b2, b3);
            }
        }
#pragma unroll
        for (int i = 0; i < 8; i++) {
            s[i][0] *= 0.125f; s[i][1] *= 0.125f; s[i][2] *= 0.125f; s[i][3] *= 0.125f;
        }
        if (kt == qt) {
            int r0 = (wid << 4) + (lane >> 2);
#pragma unroll
            for (int nf = 0; nf < 8; nf++) {
                int c0 = (nf << 3) + ((lane & 3) << 1);
                if (c0     > r0)     s[nf][0] = -1e30f;
                if (c0 + 1 > r0)     s[nf][1] = -1e30f;
                if (c0     > r0 + 8) s[nf][2] = -1e30f;
                if (c0 + 1 > r0 + 8) s[nf][3] = -1e30f;
            }
        }

        float mx0 = s[0][0], mx1 = s[0][2];
#pragma unroll
        for (int nf = 0; nf < 8; nf++) {
            mx0 = fmaxf(mx0, fmaxf(s[nf][0], s[nf][1]));
            mx1 = fmaxf(mx1, fmaxf(s[nf][2], s[nf][3]));
        }
        mx0 = fmaxf(mx0, __shfl_xor_sync(0xffffffffu, mx0, 1));
        mx0 = fmaxf(mx0, __shfl_xor_sync(0xffffffffu, mx0, 2));
        mx1 = fmaxf(mx1, __shfl_xor_sync(0xffffffffu, mx1, 1));
        mx1 = fmaxf(mx1, __shfl_xor_sync(0xffffffffu, mx1, 2));
        float mn0 = fmaxf(m0, mx0), mn1 = fmaxf(m1, mx1);
        float cr0 = __expf(m0 - mn0), cr1 = __expf(m1 - mn1);
        float rs0 = 0.f, rs1 = 0.f;
        uint32_t pa[4][4];
#pragma unroll
        for (int nf = 0; nf < 8; nf++) {
            float p0 = __expf(s[nf][0] - mn0);
            float p1 = __expf(s[nf][1] - mn0);
            float p2 = __expf(s[nf][2] - mn1);
            float p3 = __expf(s[nf][3] - mn1);
            rs0 += p0 + p1; rs1 += p2 + p3;
            __half2 h01 = __floats2half2_rn(p0, p1);
            __half2 h23 = __floats2half2_rn(p2, p3);
            int kc = nf >> 1, hi = (nf & 1) << 1;
            pa[kc][hi]     = *(uint32_t*)&h01;
            pa[kc][hi + 1] = *(uint32_t*)&h23;
        }
        rs0 += __shfl_xor_sync(0xffffffffu, rs0, 1);
        rs0 += __shfl_xor_sync(0xffffffffu, rs0, 2);
        rs1 += __shfl_xor_sync(0xffffffffu, rs1, 1);
        rs1 += __shfl_xor_sync(0xffffffffu, rs1, 2);
        l0 = l0 * cr0 + rs0; l1 = l1 * cr1 + rs1;
        m0 = mn0; m1 = mn1;
#pragma unroll
        for (int i = 0; i < 8; i++) {
            oa[i][0] *= cr0; oa[i][1] *= cr0; oa[i][2] *= cr1; oa[i][3] *= cr1;
        }

        uint32_t rV = (lane & 7) + (((lane >> 3) & 1) << 3);
        uint32_t cV = ((lane >> 4) & 1) << 3;
#pragma unroll
        for (int kc = 0; kc < 4; kc++) {
#pragma unroll
            for (int p = 0; p < 4; p++) {
                uint32_t b0, b1, b2, b3;
                ldsm4t(b0, b1, b2, b3,
                       sVt + ((((uint32_t)(kc << 4) + rV) * AT_PAD + (uint32_t)(p << 4) + cV) << 1));
                mma_f16(oa[2*p][0], oa[2*p][1], oa[2*p][2], oa[2*p][3],
                        pa[kc][0], pa[kc][1], pa[kc][2], pa[kc][3], b0, b1);
                mma_f16(oa[2*p+1][0], oa[2*p+1][1], oa[2*p+1][2], oa[2*p+1][3],
                        pa[kc][0], pa[kc][1], pa[kc][2], pa[kc][3], b2, b3);
            }
        }
    }

    float i0 = 1.0f / l0, i1 = 1.0f / l1;
    int r0 = qt * 64 + (wid << 4) + (lane >> 2);
    __half* ob = outb + (size_t)(b * T_SEQ) * C_DIM + hh * 64;
#pragma unroll
    for (int nf = 0; nf < 8; nf++) {
        int c = (nf << 3) + ((lane & 3) << 1);
        __half2 h0 = __floats2half2_rn(oa[nf][0] * i0, oa[nf][1] * i0);
        __half2 h1 = __floats2half2_rn(oa[nf][2] * i1, oa[nf][3] * i1);
        *(__half2*)(ob + (size_t)r0 * C_DIM + c)       = h0;
        *(__half2*)(ob + (size_t)(r0 + 8) * C_DIM + c) = h1;
    }
}

// ---------------- smem sizes per instantiation (BK=64, 2-stage) ----------------
#define GSM_128_NK  ((128 * ROWH + 128 * ROWH) * 2 * 2)   // 73728
#define GSM_64_NK   ((64 * ROWH + 128 * ROWH) * 2 * 2)    // 55296
#define GSM_128_KN  ((128 * ROWH + 64 * ROWB) * 2 * 2)    // 71680
#define GSM_64_KN   ((64 * ROWH + 64 * ROWB) * 2 * 2)     // 53248

// ---------------- launcher ----------------
extern "C" void kernel_launch(void* const* d_in, const int* in_sizes, int n_in,
                              void* d_out, int out_size)
{
    const int*   idx    = (const int*)  d_in[0];
    const float* tok    = (const float*)d_in[1];
    const float* pos    = (const float*)d_in[2];
    const float* ln1_s  = (const float*)d_in[3];
    const float* ln1_b  = (const float*)d_in[4];
    const float* Wq     = (const float*)d_in[5];
    const float* Wk     = (const float*)d_in[6];
    const float* Wv     = (const float*)d_in[7];
    const float* Wo     = (const float*)d_in[8];
    const float* bo     = (const float*)d_in[9];
    const float* ln2_s  = (const float*)d_in[10];
    const float* ln2_b  = (const float*)d_in[11];
    const float* W1     = (const float*)d_in[12];
    const float* b1     = (const float*)d_in[13];
    const float* W2     = (const float*)d_in[14];
    const float* b2     = (const float*)d_in[15];
    const float* lnf_s  = (const float*)d_in[16];
    const float* lnf_b  = (const float*)d_in[17];
    float* out = (float*)d_out;

    float *x;
    __half *qkvh, *hh, *ffh, *wph, *woh, *w1h, *w2h, *tokh;
    cudaGetSymbolAddress((void**)&x,     g_x);
    cudaGetSymbolAddress((void**)&qkvh,  g_qkvh);
    cudaGetSymbolAddress((void**)&hh,    g_hh);
    cudaGetSymbolAddress((void**)&ffh,   g_ffh);
    cudaGetSymbolAddress((void**)&wph,   g_wph);
    cudaGetSymbolAddress((void**)&woh,   g_woh);
    cudaGetSymbolAddress((void**)&w1h,   g_w1h);
    cudaGetSymbolAddress((void**)&w2h,   g_w2h);
    cudaGetSymbolAddress((void**)&tokh,  g_tokh);

    cudaFuncSetAttribute(hgemm<64,1,1>,  cudaFuncAttributeMaxDynamicSharedMemorySize, GSM_64_NK);
    cudaFuncSetAttribute(hgemm<128,0,1>, cudaFuncAttributeMaxDynamicSharedMemorySize, GSM_128_NK);
    cudaFuncSetAttribute(hgemm<64,1,0>,  cudaFuncAttributeMaxDynamicSharedMemorySize, GSM_64_KN);
    cudaFuncSetAttribute(hgemm<64,0,0>,  cudaFuncAttributeMaxDynamicSharedMemorySize, GSM_64_KN);

    // ---- one-time per call: weight conversion ----
    k_cvt<<<(V_SZ * C_DIM) / 2048, 256>>>(tok, tokh);
    k_cvt<<<(L_NUM * C_DIM * C_DIM) / 2048, 256>>>(Wo, woh);
    k_cvt<<<(L_NUM * C_DIM * FF_DIM) / 2048, 256>>>(W1, w1h);
    k_cvt<<<(L_NUM * FF_DIM * C_DIM) / 2048, 256>>>(W2, w2h);
    k_packQKV<<<L_NUM * 1536, 256>>>(Wq, Wk, Wv, wph);
    k_embed<<<M_ROWS, 256>>>(idx, tok, pos, x);

    for (int l = 0; l < L_NUM; l++) {
        // LN1 -> half
        k_ln<<<M_ROWS, 256>>>(x, ln1_s + l * C_DIM, ln1_b + l * C_DIM, hh);
        // qkv = hh @ wph^T -> half   (MT=64: 768 CTAs @ 3/SM)
        hgemm<64,1,1><<<dim3(3072 / 128, M_ROWS / 64), 256, GSM_64_NK>>>(
            hh, wph + (size_t)l * 3 * C_DIM * C_DIM, qkvh, nullptr, nullptr, 3072, C_DIM, 0);
        // tensor-core flash attention -> hh
        k_attn<<<dim3(T_SEQ / 64, B_SZ * H_NUM), 128>>>(qkvh, hh);
        // x = x + hh @ Wo + bo   (Wo [K,N], MT=64)
        hgemm<64,0,0><<<dim3(C_DIM / 128, M_ROWS / 64), 256, GSM_64_KN>>>(
            hh, woh + (size_t)l * C_DIM * C_DIM, x, bo + l * C_DIM, x, C_DIM, C_DIM, 0);
        // LN2 -> half
        k_ln<<<M_ROWS, 256>>>(x, ln2_s + l * C_DIM, ln2_b + l * C_DIM, hh);
        // ffh = relu(hh @ W1 + b1) -> half  (W1 [K,N], MT=64: 1024 CTAs @ 3/SM)
        hgemm<64,1,0><<<dim3(FF_DIM / 128, M_ROWS / 64), 256, GSM_64_KN>>>(
            hh, w1h + (size_t)l * C_DIM * FF_DIM, ffh, b1 + l * FF_DIM, nullptr, FF_DIM, C_DIM, 1);
        // x = x + ffh @ W2 + b2  (W2 [K,N], MT=64)
        hgemm<64,0,0><<<dim3(C_DIM / 128, M_ROWS / 64), 256, GSM_64_KN>>>(
            ffh, w2h + (size_t)l * FF_DIM * C_DIM, x, b2 + l * C_DIM, x, C_DIM, FF_DIM, 0);
    }

    // final LN + tied-embedding logits (tok [V,K] -> MT=128 TRB=1, many waves)
    k_ln<<<M_ROWS, 256>>>(x, lnf_s, lnf_b, hh);
    hgemm<128,0,1><<<dim3(V_SZ / 128, M_ROWS / 128), 256, GSM_128_NK>>>(
        hh, tokh, out, nullptr, nullptr, V_SZ, C_DIM, 0);
}

// round 14
// speedup vs baseline: 1.0019x; 1.0001x over previous
#include <cuda_runtime.h>
#include <cuda_fp16.h>
#include <cstdint>
#include <math.h>

// ---------------- model constants ----------------
#define C_DIM   1024
#define H_NUM   16
#define D_HEAD  64
#define L_NUM   8
#define T_SEQ   1024
#define B_SZ    2
#define M_ROWS  (B_SZ * T_SEQ)      // 2048
#define FF_DIM  4096
#define V_SZ    32000

// ---------------- device scratch ----------------
__device__ __align__(256) float  g_x   [M_ROWS * C_DIM];            // residual (fp32)
__device__ __align__(256) __half g_qkvh[M_ROWS * 3 * C_DIM];        // qkv (half)
__device__ __align__(256) __half g_hh  [M_ROWS * C_DIM];            // LN out / attn out
__device__ __align__(256) __half g_ffh [M_ROWS * FF_DIM];           // relu FF out
__device__ __align__(256) __half g_wph [L_NUM * 3 * C_DIM * C_DIM]; // qkv W [N,K] all layers
__device__ __align__(256) __half g_woh [L_NUM * C_DIM * C_DIM];     // Wo half [K,N]
__device__ __align__(256) __half g_w1h [L_NUM * C_DIM * FF_DIM];    // W1 half [K,N]
__device__ __align__(256) __half g_w2h [L_NUM * FF_DIM * C_DIM];    // W2 half [K,N]
__device__ __align__(256) __half g_tokh[V_SZ * C_DIM];              // tok [V,K]

// ============================================================
// helpers
// ============================================================
__device__ __forceinline__ uint32_t smem_u32(const void* p) {
    uint32_t a;
    asm("{ .reg .u64 t; cvta.to.shared.u64 t, %1; cvt.u32.u64 %0, t; }" : "=r"(a) : "l"(p));
    return a;
}
__device__ __forceinline__ void cpa16(uint32_t dst, const void* src) {
    asm volatile("cp.async.cg.shared.global [%0], [%1], 16;" :: "r"(dst), "l"(src));
}
__device__ __forceinline__ void ldsm4(uint32_t& r0, uint32_t& r1, uint32_t& r2, uint32_t& r3,
                                      uint32_t a) {
    asm volatile("ldmatrix.sync.aligned.m8n8.x4.shared.b16 {%0,%1,%2,%3}, [%4];"
        : "=r"(r0), "=r"(r1), "=r"(r2), "=r"(r3) : "r"(a));
}
__device__ __forceinline__ void ldsm4t(uint32_t& r0, uint32_t& r1, uint32_t& r2, uint32_t& r3,
                                       uint32_t a) {
    asm volatile("ldmatrix.sync.aligned.m8n8.x4.trans.shared.b16 {%0,%1,%2,%3}, [%4];"
        : "=r"(r0), "=r"(r1), "=r"(r2), "=r"(r3) : "r"(a));
}
__device__ __forceinline__ void mma_f16(float& c0, float& c1, float& c2, float& c3,
                                        uint32_t a0, uint32_t a1, uint32_t a2, uint32_t a3,
                                        uint32_t b0, uint32_t b1) {
    asm volatile("mma.sync.aligned.m16n8k16.row.col.f32.f16.f16.f32 "
        "{%0,%1,%2,%3}, {%4,%5,%6,%7}, {%8,%9}, {%0,%1,%2,%3};"
        : "+f"(c0), "+f"(c1), "+f"(c2), "+f"(c3)
        : "r"(a0), "r"(a1), "r"(a2), "r"(a3), "r"(b0), "r"(b1));
}

// ============================================================
// FP16 mma.sync GEMM: C[M,N] = A[M,K] @ B.  BK=64, 2-stage cp.async.
//   MT:  CTA M-tile (128 or 64); N-tile 128. 256 threads, 8 warps (2x4).
//   TRB=1: B stored [N,K] (A @ B^T), ldsm non-trans.
//   TRB=0: B stored [K,N] natural,  ldsm trans.
//   OUTH=1: half out (+bias)(+relu). OUTH=0: fp32 out (+bias)(+res).
// ============================================================
#define ROWH  72        // A / B-NK row pitch (64 + 8 pad halves)
#define ROWB  136       // B-KN row pitch (128 + 8 pad halves)

template<int MT, int OUTH, int TRB>
__global__ __launch_bounds__(256, MT == 64 ? 3 : 2)
void hgemm(const __half* __restrict__ A, const __half* __restrict__ B,
           void* __restrict__ Cout, const float* __restrict__ bias,
           const float* __restrict__ res, int N, int K, int relu)
{
    constexpr int MF      = MT / 32;                       // m-frags per warp
    constexpr int A_TILE  = MT * ROWH;                     // halves
    constexpr int B_TILE  = TRB ? 128 * ROWH : 64 * ROWB;  // halves
    constexpr int STAGE_B = (A_TILE + B_TILE) * 2;         // bytes

    extern __shared__ __half smh[];
    uint32_t sbase = smem_u32(smh);
    int tid  = threadIdx.x;
    int wid  = tid >> 5;
    int lane = tid & 31;
    int wm   = wid >> 2;          // 0..1
    int wn   = wid & 3;           // 0..3
    int bm = blockIdx.y * MT;
    int bn = blockIdx.x << 7;

    const __half* Ag = A + (size_t)bm * K;
    int NC = K >> 6;

    float acc[MF][4][4];
#pragma unroll
    for (int mf = 0; mf < MF; mf++)
#pragma unroll
        for (int nf = 0; nf < 4; nf++)
#pragma unroll
            for (int k = 0; k < 4; k++) acc[mf][nf][k] = 0.f;

    auto load_tile = [&](int ch, int stage) {
        int k0 = ch << 6;
        uint32_t so = sbase + (uint32_t)stage * STAGE_B;
        uint32_t bo = so + (uint32_t)A_TILE * 2u;
#pragma unroll
        for (int i = 0; i < MT / 32; i++) {                // A: MT rows x 64 k
            int id = tid + (i << 8);
            int r = id >> 3, c = (id & 7) << 3;
            cpa16(so + ((uint32_t)(r * ROWH + c) << 1), Ag + (size_t)r * K + k0 + c);
        }
        if (TRB) {                                         // B: 128 n-rows x 64 k
            const __half* Bg = B + (size_t)bn * K;
#pragma unroll
            for (int i = 0; i < 4; i++) {
                int id = tid + (i << 8);
                int r = id >> 3, c = (id & 7) << 3;
                cpa16(bo + ((uint32_t)(r * ROWH + c) << 1), Bg + (size_t)r * K + k0 + c);
            }
        } else {                                           // B: 64 k-rows x 128 n
#pragma unroll
            for (int i = 0; i < 4; i++) {
                int id = tid + (i << 8);
                int r = id >> 4, c = (id & 15) << 3;
                cpa16(bo + ((uint32_t)(r * ROWB + c) << 1),
                      B + (size_t)(k0 + r) * N + bn + c);
            }
        }
    };

    load_tile(0, 0);
    asm volatile("cp.async.commit_group;");

    uint32_t rA = (uint32_t)(wm * (MT / 2)) + (lane & 7) + (((lane >> 3) & 1) << 3);
    uint32_t kA = ((lane >> 4) & 1) << 3;
    uint32_t rB = (uint32_t)(wn << 5) + (lane & 7) + (((lane >> 4) & 1) << 3);
    uint32_t kB = ((lane >> 3) & 1) << 3;
    uint32_t rBt = (lane & 7) + (((lane >> 3) & 1) << 3);
    uint32_t cBt = (uint32_t)(wn << 5) + (((lane >> 4) & 1) << 3);

    for (int ch = 0; ch < NC; ch++) {
        if (ch > 0) __syncthreads();
        if (ch + 1 < NC) load_tile(ch + 1, (ch + 1) & 1);
        asm volatile("cp.async.commit_group;");
        asm volatile("cp.async.wait_group 1;");
        __syncthreads();

        uint32_t sA = sbase + (uint32_t)(ch & 1) * STAGE_B;
        uint32_t sB = sA + (uint32_t)A_TILE * 2u;
#pragma unroll
        for (int ks = 0; ks < 4; ks++) {
            uint32_t af[MF][4], bf[4][2];
            uint32_t kofs = (uint32_t)(ks << 4);
#pragma unroll
            for (int mf = 0; mf < MF; mf++) {
                uint32_t a = sA + (((rA + (uint32_t)(mf << 4)) * ROWH + kA + kofs) << 1);
                ldsm4(af[mf][0], af[mf][1], af[mf][2], af[mf][3], a);
            }
            if (TRB) {
#pragma unroll
                for (int p = 0; p < 2; p++) {
                    uint32_t a = sB + (((rB + (uint32_t)(p << 4)) * ROWH + kB + kofs) << 1);
                    ldsm4(bf[2 * p][0], bf[2 * p][1], bf[2 * p + 1][0], bf[2 * p + 1][1], a);
                }
            } else {
#pragma unroll
                for (int p = 0; p < 2; p++) {
                    uint32_t a = sB + (((kofs + rBt) * ROWB + cBt + (uint32_t)(p << 4)) << 1);
                    ldsm4t(bf[2 * p][0], bf[2 * p][1], bf[2 * p + 1][0], bf[2 * p + 1][1], a);
                }
            }
#pragma unroll
            for (int mf = 0; mf < MF; mf++)
#pragma unroll
                for (int nf = 0; nf < 4; nf++)
                    mma_f16(acc[mf][nf][0], acc[mf][nf][1], acc[mf][nf][2], acc[mf][nf][3],
                            af[mf][0], af[mf][1], af[mf][2], af[mf][3],
                            bf[nf][0], bf[nf][1]);
        }
    }

    // ---- epilogue ----
    int row0 = bm + wm * (MT / 2) + (lane >> 2);
    int col0 = bn + (wn << 5) + ((lane & 3) << 1);
#pragma unroll
    for (int mf = 0; mf < MF; mf++) {
#pragma unroll
        for (int half_ = 0; half_ < 2; half_++) {
            int row = row0 + (mf << 4) + half_ * 8;
#pragma unroll
            for (int nf = 0; nf < 4; nf++) {
                float vx = acc[mf][nf][half_ * 2 + 0];
                float vy = acc[mf][nf][half_ * 2 + 1];
                int c = (nf << 3);
                if (bias) {
                    vx += bias[col0 + c];
                    vy += bias[col0 + c + 1];
                }
                if (OUTH) {
                    if (relu) { vx = fmaxf(vx, 0.f); vy = fmaxf(vy, 0.f); }
                    __half2 hv = __floats2half2_rn(vx, vy);
                    *(__half2*)((__half*)Cout + (size_t)row * N + col0 + c) = hv;
                } else {
                    if (res) {
                        const float* rp = res + (size_t)row * N + col0 + c;
                        float2 r2 = *(const float2*)rp;
                        vx += r2.x; vy += r2.y;
                    }
                    float2 v; v.x = vx; v.y = vy;
                    *(float2*)((float*)Cout + (size_t)row * N + col0 + c) = v;
                }
            }
        }
    }
}

// ---------------- embedding ----------------
__global__ void k_embed(const int* __restrict__ idx,
                        const float* __restrict__ tok,
                        const float* __restrict__ pos,
                        float* __restrict__ x)
{
    int m = blockIdx.x;
    int c = threadIdx.x * 4;
    int t = m & (T_SEQ - 1);
    int v = idx[m];
    float4 a = *(const float4*)(tok + (size_t)v * C_DIM + c);
    float4 p = *(const float4*)(pos + (size_t)t * C_DIM + c);
    a.x += p.x; a.y += p.y; a.z += p.z; a.w += p.w;
    *(float4*)(x + (size_t)m * C_DIM + c) = a;
}

// ---------------- layernorm: fp32 in -> fp16 out ----------------
__global__ void k_ln(const float* __restrict__ x,
                     const float* __restrict__ sc,
                     const float* __restrict__ bi,
                     __half* __restrict__ out)
{
    int m = blockIdx.x;
    int tid = threadIdx.x;                 // 256 threads
    int c = tid * 4;
    float4 v = *(const float4*)(x + (size_t)m * C_DIM + c);
    float s = v.x + v.y + v.z + v.w;
    float q = v.x*v.x + v.y*v.y + v.z*v.z + v.w*v.w;

    __shared__ float rs[8], rq[8];
#pragma unroll
    for (int o = 16; o > 0; o >>= 1) {
        s += __shfl_xor_sync(0xffffffffu, s, o);
        q += __shfl_xor_sync(0xffffffffu, q, o);
    }
    if ((tid & 31) == 0) { rs[tid >> 5] = s; rq[tid >> 5] = q; }
    __syncthreads();
    float sum = 0.f, sq = 0.f;
#pragma unroll
    for (int w = 0; w < 8; w++) { sum += rs[w]; sq += rq[w]; }

    float mu = sum * (1.0f / C_DIM);
    float var = sq * (1.0f / C_DIM) - mu * mu;
    float rstd = rsqrtf(var + 1e-5f);

    float4 svv = *(const float4*)(sc + c);
    float4 bvv = *(const float4*)(bi + c);
    __half2 p0 = __floats2half2_rn((v.x - mu) * rstd * svv.x + bvv.x,
                                   (v.y - mu) * rstd * svv.y + bvv.y);
    __half2 p1 = __floats2half2_rn((v.z - mu) * rstd * svv.z + bvv.z,
                                   (v.w - mu) * rstd * svv.w + bvv.w);
    uint2 st;
    st.x = *(uint32_t*)&p0;
    st.y = *(uint32_t*)&p1;
    *(uint2*)(out + (size_t)m * C_DIM + c) = st;
}

// ---------------- pack qkv weights ALL layers -> [L][3C, C] half ----------------
__global__ __launch_bounds__(256)
void k_packQKV(const float* __restrict__ Wq, const float* __restrict__ Wk,
               const float* __restrict__ Wv, __half* __restrict__ out)
{
    __shared__ float t[32][65];
    int b  = blockIdx.x;
    int l  = b / 1536;
    b -= l * 1536;
    int kb = b & 31;
    int hh = (b >> 5) & 15;
    int s  = b >> 9;
    const float* W = (s == 0) ? Wq : ((s == 1) ? Wk : Wv);
    const float* Wb = W + ((size_t)l * H_NUM + hh) * C_DIM * D_HEAD + (size_t)(kb << 5) * D_HEAD;
    int tid = threadIdx.x;
#pragma unroll
    for (int i = 0; i < 8; i++) {
        int idx = tid + (i << 8);
        int r = idx >> 6, d = idx & 63;
        t[r][d] = Wb[(size_t)r * D_HEAD + d];
    }
    __syncthreads();
    __half* outl = out + (size_t)l * 3 * C_DIM * C_DIM;
    int n0 = s * 1024 + hh * 64;
#pragma unroll
    for (int i = 0; i < 8; i++) {
        int idx = tid + (i << 8);
        int d = idx >> 5, kk = idx & 31;
        outl[(size_t)(n0 + d) * C_DIM + (kb << 5) + kk] = __float2half_rn(t[kk][d]);
    }
}

// ---------------- pure fp32 -> fp16 convert (layout preserved) ----------------
__global__ __launch_bounds__(256)
void k_cvt(const float* __restrict__ in, __half* __restrict__ out)
{
    size_t i = ((size_t)blockIdx.x * 256 + threadIdx.x) * 8;
    float4 a = *(const float4*)(in + i);
    float4 b = *(const float4*)(in + i + 4);
    __half2 h0 = __floats2half2_rn(a.x, a.y);
    __half2 h1 = __floats2half2_rn(a.z, a.w);
    __half2 h2 = __floats2half2_rn(b.x, b.y);
    __half2 h3 = __floats2half2_rn(b.z, b.w);
    uint4 st;
    st.x = *(uint32_t*)&h0; st.y = *(uint32_t*)&h1;
    st.z = *(uint32_t*)&h2; st.w = *(uint32_t*)&h3;
    *(uint4*)(out + i) = st;
}

// ============================================================
// Tensor-core causal flash attention.
// ============================================================
#define AT_PAD  72
#define AT_TILEB (64 * AT_PAD * 2)

__global__ __launch_bounds__(128)
void k_attn(const __half* __restrict__ qkvh, __half* __restrict__ outb)
{
    __shared__ __half Qs[64][AT_PAD];
    __shared__ __half Ks[2][64][AT_PAD];
    __shared__ __half Vs[2][64][AT_PAD];

    int qt = blockIdx.x;
    int b  = blockIdx.y >> 4;
    int hh = blockIdx.y & 15;
    int tid = threadIdx.x;
    int wid = tid >> 5, lane = tid & 31;

    const __half* qp = qkvh + ((size_t)(b * T_SEQ + qt * 64)) * 3072 + hh * 64;
    const __half* kp = qkvh + ((size_t)(b * T_SEQ)) * 3072 + 1024 + hh * 64;
    const __half* vp = kp + 1024;

    uint32_t sQ = smem_u32(Qs);
    uint32_t sK = smem_u32(Ks);
    uint32_t sV = smem_u32(Vs);

#pragma unroll
    for (int i = 0; i < 4; i++) {
        int id = tid + (i << 7);
        int r = id >> 3, c = (id & 7) << 3;
        uint32_t off = (uint32_t)(r * AT_PAD + c) << 1;
        cpa16(sQ + off, qp + (size_t)r * 3072 + c);
        cpa16(sK + off, kp + (size_t)r * 3072 + c);
        cpa16(sV + off, vp + (size_t)r * 3072 + c);
    }
    asm volatile("cp.async.commit_group;");

    uint32_t qf[4][4];
    float oa[8][4];
    float m0 = -1e30f, m1 = -1e30f, l0 = 0.f, l1 = 0.f;
#pragma unroll
    for (int i = 0; i < 8; i++) { oa[i][0] = oa[i][1] = oa[i][2] = oa[i][3] = 0.f; }

    for (int kt = 0; kt <= qt; kt++) {
        if (kt > 0) __syncthreads();
        if (kt < qt) {
            uint32_t st = (uint32_t)((kt + 1) & 1) * AT_TILEB;
#pragma unroll
            for (int i = 0; i < 4; i++) {
                int id = tid + (i << 7);
                int r = id >> 3, c = (id & 7) << 3;
                uint32_t off = (uint32_t)(r * AT_PAD + c) << 1;
                cpa16(sK + st + off, kp + (size_t)((kt + 1) * 64 + r) * 3072 + c);
                cpa16(sV + st + off, vp + (size_t)((kt + 1) * 64 + r) * 3072 + c);
            }
        }
        asm volatile("cp.async.commit_group;");
        asm volatile("cp.async.wait_group 1;");
        __syncthreads();

        if (kt == 0) {
            uint32_t rAq = (uint32_t)(wid << 4) + (lane & 7) + (((lane >> 3) & 1) << 3);
#pragma unroll
            for (int kc = 0; kc < 4; kc++) {
                uint32_t kAq = (((lane >> 4) & 1) << 3) + (kc << 4);
                ldsm4(qf[kc][0], qf[kc][1], qf[kc][2], qf[kc][3],
                      sQ + ((rAq * AT_PAD + kAq) << 1));
            }
        }

        uint32_t sKt = sK + (uint32_t)(kt & 1) * AT_TILEB;
        uint32_t sVt = sV + (uint32_t)(kt & 1) * AT_TILEB;

        float s[8][4];
#pragma unroll
        for (int i = 0; i < 8; i++) { s[i][0] = s[i][1] = s[i][2] = s[i][3] = 0.f; }
        uint32_t rBk = (lane & 7) + (((lane >> 4) & 1) << 3);
        uint32_t kBo = ((lane >> 3) & 1) << 3;
#pragma unroll
        for (int kc = 0; kc < 4; kc++) {
#pragma unroll
            for (int p = 0; p < 4; p++) {
                uint32_t b0, b1, b2, b3;
                ldsm4(b0, b1, b2, b3,
                      sKt + (((rBk + (uint32_t)(p << 4)) * AT_PAD + kBo + (kc << 4)) << 1));
                mma_f16(s[2*p][0], s[2*p][1], s[2*p][2], s[2*p][3],
                        qf[kc][0], qf[kc][1], qf[kc][2], qf[kc][3], b0, b1);
                mma_f16(s[2*p+1][0], s[2*p+1][1], s[2*p+1][2], s[2*p+1][3],
                        qf[kc][0], qf[kc][1], qf[kc][2], qf[kc][3], b2, b3);
            }
        }
#pragma unroll
        for (int i = 0; i < 8; i++) {
            s[i][0] *= 0.125f; s[i][1] *= 0.125f; s[i][2] *= 0.125f; s[i][3] *= 0.125f;
        }
        if (kt == qt) {
            int r0 = (wid << 4) + (lane >> 2);
#pragma unroll
            for (int nf = 0; nf < 8; nf++) {
                int c0 = (nf << 3) + ((lane & 3) << 1);
                if (c0     > r0)     s[nf][0] = -1e30f;
                if (c0 + 1 > r0)     s[nf][1] = -1e30f;
                if (c0     > r0 + 8) s[nf][2] = -1e30f;
                if (c0 + 1 > r0 + 8) s[nf][3] = -1e30f;
            }
        }

        float mx0 = s[0][0], mx1 = s[0][2];
#pragma unroll
        for (int nf = 0; nf < 8; nf++) {
            mx0 = fmaxf(mx0, fmaxf(s[nf][0], s[nf][1]));
            mx1 = fmaxf(mx1, fmaxf(s[nf][2], s[nf][3]));
        }
        mx0 = fmaxf(mx0, __shfl_xor_sync(0xffffffffu, mx0, 1));
        mx0 = fmaxf(mx0, __shfl_xor_sync(0xffffffffu, mx0, 2));
        mx1 = fmaxf(mx1, __shfl_xor_sync(0xffffffffu, mx1, 1));
        mx1 = fmaxf(mx1, __shfl_xor_sync(0xffffffffu, mx1, 2));
        float mn0 = fmaxf(m0, mx0), mn1 = fmaxf(m1, mx1);
        float cr0 = __expf(m0 - mn0), cr1 = __expf(m1 - mn1);
        float rs0 = 0.f, rs1 = 0.f;
        uint32_t pa[4][4];
#pragma unroll
        for (int nf = 0; nf < 8; nf++) {
            float p0 = __expf(s[nf][0] - mn0);
            float p1 = __expf(s[nf][1] - mn0);
            float p2 = __expf(s[nf][2] - mn1);
            float p3 = __expf(s[nf][3] - mn1);
            rs0 += p0 + p1; rs1 += p2 + p3;
            __half2 h01 = __floats2half2_rn(p0, p1);
            __half2 h23 = __floats2half2_rn(p2, p3);
            int kc = nf >> 1, hi = (nf & 1) << 1;
            pa[kc][hi]     = *(uint32_t*)&h01;
            pa[kc][hi + 1] = *(uint32_t*)&h23;
        }
        rs0 += __shfl_xor_sync(0xffffffffu, rs0, 1);
        rs0 += __shfl_xor_sync(0xffffffffu, rs0, 2);
        rs1 += __shfl_xor_sync(0xffffffffu, rs1, 1);
        rs1 += __shfl_xor_sync(0xffffffffu, rs1, 2);
        l0 = l0 * cr0 + rs0; l1 = l1 * cr1 + rs1;
        m0 = mn0; m1 = mn1;
#pragma unroll
        for (int i = 0; i < 8; i++) {
            oa[i][0] *= cr0; oa[i][1] *= cr0; oa[i][2] *= cr1; oa[i][3] *= cr1;
        }

        uint32_t rV = (lane & 7) + (((lane >> 3) & 1) << 3);
        uint32_t cV = ((lane >> 4) & 1) << 3;
#pragma unroll
        for (int kc = 0; kc < 4; kc++) {
#pragma unroll
            for (int p = 0; p < 4; p++) {
                uint32_t b0, b1, b2, b3;
                ldsm4t(b0, b1, b2, b3,
                       sVt + ((((uint32_t)(kc << 4) + rV) * AT_PAD + (uint32_t)(p << 4) + cV) << 1));
                mma_f16(oa[2*p][0], oa[2*p][1], oa[2*p][2], oa[2*p][3],
                        pa[kc][0], pa[kc][1], pa[kc][2], pa[kc][3], b0, b1);
                mma_f16(oa[2*p+1][0], oa[2*p+1][1], oa[2*p+1][2], oa[2*p+1][3],
                        pa[kc][0], pa[kc][1], pa[kc][2], pa[kc][3], b2, b3);
            }
        }
    }

    float i0 = 1.0f / l0, i1 = 1.0f / l1;
    int r0 = qt * 64 + (wid << 4) + (lane >> 2);
    __half* ob = outb + (size_t)(b * T_SEQ) * C_DIM + hh * 64;
#pragma unroll
    for (int nf = 0; nf < 8; nf++) {
        int c = (nf << 3) + ((lane & 3) << 1);
        __half2 h0 = __floats2half2_rn(oa[nf][0] * i0, oa[nf][1] * i0);
        __half2 h1 = __floats2half2_rn(oa[nf][2] * i1, oa[nf][3] * i1);
        *(__half2*)(ob + (size_t)r0 * C_DIM + c)       = h0;
        *(__half2*)(ob + (size_t)(r0 + 8) * C_DIM + c) = h1;
    }
}

// ---------------- smem sizes per instantiation (BK=64, 2-stage) ----------------
#define GSM_128_NK  ((128 * ROWH + 128 * ROWH) * 2 * 2)   // 73728
#define GSM_64_NK   ((64 * ROWH + 128 * ROWH) * 2 * 2)    // 55296
#define GSM_128_KN  ((128 * ROWH + 64 * ROWB) * 2 * 2)    // 71680
#define GSM_64_KN   ((64 * ROWH + 64 * ROWB) * 2 * 2)     // 53248

// ---------------- launcher ----------------
extern "C" void kernel_launch(void* const* d_in, const int* in_sizes, int n_in,
                              void* d_out, int out_size)
{
    const int*   idx    = (const int*)  d_in[0];
    const float* tok    = (const float*)d_in[1];
    const float* pos    = (const float*)d_in[2];
    const float* ln1_s  = (const float*)d_in[3];
    const float* ln1_b  = (const float*)d_in[4];
    const float* Wq     = (const float*)d_in[5];
    const float* Wk     = (const float*)d_in[6];
    const float* Wv     = (const float*)d_in[7];
    const float* Wo     = (const float*)d_in[8];
    const float* bo     = (const float*)d_in[9];
    const float* ln2_s  = (const float*)d_in[10];
    const float* ln2_b  = (const float*)d_in[11];
    const float* W1     = (const float*)d_in[12];
    const float* b1     = (const float*)d_in[13];
    const float* W2     = (const float*)d_in[14];
    const float* b2     = (const float*)d_in[15];
    const float* lnf_s  = (const float*)d_in[16];
    const float* lnf_b  = (const float*)d_in[17];
    float* out = (float*)d_out;

    float *x;
    __half *qkvh, *hh, *ffh, *wph, *woh, *w1h, *w2h, *tokh;
    cudaGetSymbolAddress((void**)&x,     g_x);
    cudaGetSymbolAddress((void**)&qkvh,  g_qkvh);
    cudaGetSymbolAddress((void**)&hh,    g_hh);
    cudaGetSymbolAddress((void**)&ffh,   g_ffh);
    cudaGetSymbolAddress((void**)&wph,   g_wph);
    cudaGetSymbolAddress((void**)&woh,   g_woh);
    cudaGetSymbolAddress((void**)&w1h,   g_w1h);
    cudaGetSymbolAddress((void**)&w2h,   g_w2h);
    cudaGetSymbolAddress((void**)&tokh,  g_tokh);

    cudaFuncSetAttribute(hgemm<64,1,1>,  cudaFuncAttributeMaxDynamicSharedMemorySize, GSM_64_NK);
    cudaFuncSetAttribute(hgemm<128,0,1>, cudaFuncAttributeMaxDynamicSharedMemorySize, GSM_128_NK);
    cudaFuncSetAttribute(hgemm<64,1,0>,  cudaFuncAttributeMaxDynamicSharedMemorySize, GSM_64_KN);
    cudaFuncSetAttribute(hgemm<64,0,0>,  cudaFuncAttributeMaxDynamicSharedMemorySize, GSM_64_KN);

    // ---- one-time per call: weight conversion ----
    k_cvt<<<(V_SZ * C_DIM) / 2048, 256>>>(tok, tokh);
    k_cvt<<<(L_NUM * C_DIM * C_DIM) / 2048, 256>>>(Wo, woh);
    k_cvt<<<(L_NUM * C_DIM * FF_DIM) / 2048, 256>>>(W1, w1h);
    k_cvt<<<(L_NUM * FF_DIM * C_DIM) / 2048, 256>>>(W2, w2h);
    k_packQKV<<<L_NUM * 1536, 256>>>(Wq, Wk, Wv, wph);
    k_embed<<<M_ROWS, 256>>>(idx, tok, pos, x);

    for (int l = 0; l < L_NUM; l++) {
        // LN1 -> half
        k_ln<<<M_ROWS, 256>>>(x, ln1_s + l * C_DIM, ln1_b + l * C_DIM, hh);
        // qkv = hh @ wph^T -> half   (MT=64: 768 CTAs @ 3/SM)
        hgemm<64,1,1><<<dim3(3072 / 128, M_ROWS / 64), 256, GSM_64_NK>>>(
            hh, wph + (size_t)l * 3 * C_DIM * C_DIM, qkvh, nullptr, nullptr, 3072, C_DIM, 0);
        // tensor-core flash attention -> hh
        k_attn<<<dim3(T_SEQ / 64, B_SZ * H_NUM), 128>>>(qkvh, hh);
        // x = x + hh @ Wo + bo   (Wo [K,N], MT=64)
        hgemm<64,0,0><<<dim3(C_DIM / 128, M_ROWS / 64), 256, GSM_64_KN>>>(
            hh, woh + (size_t)l * C_DIM * C_DIM, x, bo + l * C_DIM, x, C_DIM, C_DIM, 0);
        // LN2 -> half
        k_ln<<<M_ROWS, 256>>>(x, ln2_s + l * C_DIM, ln2_b + l * C_DIM, hh);
        // ffh = relu(hh @ W1 + b1) -> half  (W1 [K,N], MT=64: 1024 CTAs @ 3/SM)
        hgemm<64,1,0><<<dim3(FF_DIM / 128, M_ROWS / 64), 256, GSM_64_KN>>>(
            hh, w1h + (size_t)l * C_DIM * FF_DIM, ffh, b1 + l * FF_DIM, nullptr, FF_DIM, C_DIM, 1);
        // x = x + ffh @ W2 + b2  (W2 [K,N], MT=64)
        hgemm<64,0,0><<<dim3(C_DIM / 128, M_ROWS / 64), 256, GSM_64_KN>>>(
            ffh, w2h + (size_t)l * FF_DIM * C_DIM, x, b2 + l * C_DIM, x, C_DIM, FF_DIM, 0);
    }

    // final LN + tied-embedding logits (tok [V,K] -> MT=128 TRB=1, many waves)
    k_ln<<<M_ROWS, 256>>>(x, lnf_s, lnf_b, hh);
    hgemm<128,0,1><<<dim3(V_SZ / 128, M_ROWS / 128), 256, GSM_128_NK>>>(
        hh, tokh, out, nullptr, nullptr, V_SZ, C_DIM, 0);
}

// round 15
// speedup vs baseline: 1.0035x; 1.0016x over previous
#include <cuda_runtime.h>
#include <cuda_fp16.h>
#include <cstdint>
#include <math.h>

// ---------------- model constants ----------------
#define C_DIM   1024
#define H_NUM   16
#define D_HEAD  64
#define L_NUM   8
#define T_SEQ   1024
#define B_SZ    2
#define M_ROWS  (B_SZ * T_SEQ)      // 2048
#define FF_DIM  4096
#define V_SZ    32000

// ---------------- device scratch ----------------
__device__ __align__(256) float  g_x   [M_ROWS * C_DIM];            // residual (fp32)
__device__ __align__(256) __half g_qkvh[M_ROWS * 3 * C_DIM];        // qkv (half)
__device__ __align__(256) __half g_hh  [M_ROWS * C_DIM];            // LN out / attn out
__device__ __align__(256) __half g_ffh [M_ROWS * FF_DIM];           // relu FF out
__device__ __align__(256) __half g_wph [L_NUM * 3 * C_DIM * C_DIM]; // qkv W [N,K] all layers
__device__ __align__(256) __half g_woh [L_NUM * C_DIM * C_DIM];     // Wo half [K,N]
__device__ __align__(256) __half g_w1h [L_NUM * C_DIM * FF_DIM];    // W1 half [K,N]
__device__ __align__(256) __half g_w2h [L_NUM * FF_DIM * C_DIM];    // W2 half [K,N]
__device__ __align__(256) __half g_tokh[V_SZ * C_DIM];              // tok [V,K]

// ============================================================
// helpers
// ============================================================
__device__ __forceinline__ uint32_t smem_u32(const void* p) {
    uint32_t a;
    asm("{ .reg .u64 t; cvta.to.shared.u64 t, %1; cvt.u32.u64 %0, t; }" : "=r"(a) : "l"(p));
    return a;
}
__device__ __forceinline__ void cpa16(uint32_t dst, const void* src) {
    asm volatile("cp.async.cg.shared.global [%0], [%1], 16;" :: "r"(dst), "l"(src));
}
__device__ __forceinline__ void ldsm4(uint32_t& r0, uint32_t& r1, uint32_t& r2, uint32_t& r3,
                                      uint32_t a) {
    asm volatile("ldmatrix.sync.aligned.m8n8.x4.shared.b16 {%0,%1,%2,%3}, [%4];"
        : "=r"(r0), "=r"(r1), "=r"(r2), "=r"(r3) : "r"(a));
}
__device__ __forceinline__ void ldsm4t(uint32_t& r0, uint32_t& r1, uint32_t& r2, uint32_t& r3,
                                       uint32_t a) {
    asm volatile("ldmatrix.sync.aligned.m8n8.x4.trans.shared.b16 {%0,%1,%2,%3}, [%4];"
        : "=r"(r0), "=r"(r1), "=r"(r2), "=r"(r3) : "r"(a));
}
__device__ __forceinline__ void mma_f16(float& c0, float& c1, float& c2, float& c3,
                                        uint32_t a0, uint32_t a1, uint32_t a2, uint32_t a3,
                                        uint32_t b0, uint32_t b1) {
    asm volatile("mma.sync.aligned.m16n8k16.row.col.f32.f16.f16.f32 "
        "{%0,%1,%2,%3}, {%4,%5,%6,%7}, {%8,%9}, {%0,%1,%2,%3};"
        : "+f"(c0), "+f"(c1), "+f"(c2), "+f"(c3)
        : "r"(a0), "r"(a1), "r"(a2), "r"(a3), "r"(b0), "r"(b1));
}

// ============================================================
// FP16 mma.sync GEMM: C[M,N] = A[M,K] @ B.  BK=64, 2-stage cp.async.
//   MT:  CTA M-tile (128 or 64); N-tile 128. 256 threads, 8 warps (2x4).
//   TRB=1: B stored [N,K] (A @ B^T), ldsm non-trans.
//   TRB=0: B stored [K,N] natural,  ldsm trans.
//   OUTH=1: half out (+bias)(+relu). OUTH=0: fp32 out (+bias)(+res).
// ============================================================
#define ROWH  72        // A / B-NK row pitch (64 + 8 pad halves)
#define ROWB  136       // B-KN row pitch (128 + 8 pad halves)

template<int MT, int OUTH, int TRB>
__global__ __launch_bounds__(256, MT == 64 ? 3 : 2)
void hgemm(const __half* __restrict__ A, const __half* __restrict__ B,
           void* __restrict__ Cout, const float* __restrict__ bias,
           const float* __restrict__ res, int N, int K, int relu)
{
    constexpr int MF      = MT / 32;                       // m-frags per warp
    constexpr int A_TILE  = MT * ROWH;                     // halves
    constexpr int B_TILE  = TRB ? 128 * ROWH : 64 * ROWB;  // halves
    constexpr int STAGE_B = (A_TILE + B_TILE) * 2;         // bytes

    extern __shared__ __half smh[];
    uint32_t sbase = smem_u32(smh);
    int tid  = threadIdx.x;
    int wid  = tid >> 5;
    int lane = tid & 31;
    int wm   = wid >> 2;          // 0..1
    int wn   = wid & 3;           // 0..3
    int bm = blockIdx.y * MT;
    int bn = blockIdx.x << 7;

    const __half* Ag = A + (size_t)bm * K;
    int NC = K >> 6;

    float acc[MF][4][4];
#pragma unroll
    for (int mf = 0; mf < MF; mf++)
#pragma unroll
        for (int nf = 0; nf < 4; nf++)
#pragma unroll
            for (int k = 0; k < 4; k++) acc[mf][nf][k] = 0.f;

    auto load_tile = [&](int ch, int stage) {
        int k0 = ch << 6;
        uint32_t so = sbase + (uint32_t)stage * STAGE_B;
        uint32_t bo = so + (uint32_t)A_TILE * 2u;
#pragma unroll
        for (int i = 0; i < MT / 32; i++) {                // A: MT rows x 64 k
            int id = tid + (i << 8);
            int r = id >> 3, c = (id & 7) << 3;
            cpa16(so + ((uint32_t)(r * ROWH + c) << 1), Ag + (size_t)r * K + k0 + c);
        }
        if (TRB) {                                         // B: 128 n-rows x 64 k
            const __half* Bg = B + (size_t)bn * K;
#pragma unroll
            for (int i = 0; i < 4; i++) {
                int id = tid + (i << 8);
                int r = id >> 3, c = (id & 7) << 3;
                cpa16(bo + ((uint32_t)(r * ROWH + c) << 1), Bg + (size_t)r * K + k0 + c);
            }
        } else {                                           // B: 64 k-rows x 128 n
#pragma unroll
            for (int i = 0; i < 4; i++) {
                int id = tid + (i << 8);
                int r = id >> 4, c = (id & 15) << 3;
                cpa16(bo + ((uint32_t)(r * ROWB + c) << 1),
                      B + (size_t)(k0 + r) * N + bn + c);
            }
        }
    };

    load_tile(0, 0);
    asm volatile("cp.async.commit_group;");

    uint32_t rA = (uint32_t)(wm * (MT / 2)) + (lane & 7) + (((lane >> 3) & 1) << 3);
    uint32_t kA = ((lane >> 4) & 1) << 3;
    uint32_t rB = (uint32_t)(wn << 5) + (lane & 7) + (((lane >> 4) & 1) << 3);
    uint32_t kB = ((lane >> 3) & 1) << 3;
    uint32_t rBt = (lane & 7) + (((lane >> 3) & 1) << 3);
    uint32_t cBt = (uint32_t)(wn << 5) + (((lane >> 4) & 1) << 3);

    for (int ch = 0; ch < NC; ch++) {
        if (ch > 0) __syncthreads();
        if (ch + 1 < NC) load_tile(ch + 1, (ch + 1) & 1);
        asm volatile("cp.async.commit_group;");
        asm volatile("cp.async.wait_group 1;");
        __syncthreads();

        uint32_t sA = sbase + (uint32_t)(ch & 1) * STAGE_B;
        uint32_t sB = sA + (uint32_t)A_TILE * 2u;
#pragma unroll
        for (int ks = 0; ks < 4; ks++) {
            uint32_t af[MF][4], bf[4][2];
            uint32_t kofs = (uint32_t)(ks << 4);
#pragma unroll
            for (int mf = 0; mf < MF; mf++) {
                uint32_t a = sA + (((rA + (uint32_t)(mf << 4)) * ROWH + kA + kofs) << 1);
                ldsm4(af[mf][0], af[mf][1], af[mf][2], af[mf][3], a);
            }
            if (TRB) {
#pragma unroll
                for (int p = 0; p < 2; p++) {
                    uint32_t a = sB + (((rB + (uint32_t)(p << 4)) * ROWH + kB + kofs) << 1);
                    ldsm4(bf[2 * p][0], bf[2 * p][1], bf[2 * p + 1][0], bf[2 * p + 1][1], a);
                }
            } else {
#pragma unroll
                for (int p = 0; p < 2; p++) {
                    uint32_t a = sB + (((kofs + rBt) * ROWB + cBt + (uint32_t)(p << 4)) << 1);
                    ldsm4t(bf[2 * p][0], bf[2 * p][1], bf[2 * p + 1][0], bf[2 * p + 1][1], a);
                }
            }
#pragma unroll
            for (int mf = 0; mf < MF; mf++)
#pragma unroll
                for (int nf = 0; nf < 4; nf++)
                    mma_f16(acc[mf][nf][0], acc[mf][nf][1], acc[mf][nf][2], acc[mf][nf][3],
                            af[mf][0], af[mf][1], af[mf][2], af[mf][3],
                            bf[nf][0], bf[nf][1]);
        }
    }

    // ---- epilogue ----
    int row0 = bm + wm * (MT / 2) + (lane >> 2);
    int col0 = bn + (wn << 5) + ((lane & 3) << 1);
#pragma unroll
    for (int mf = 0; mf < MF; mf++) {
#pragma unroll
        for (int half_ = 0; half_ < 2; half_++) {
            int row = row0 + (mf << 4) + half_ * 8;
#pragma unroll
            for (int nf = 0; nf < 4; nf++) {
                float vx = acc[mf][nf][half_ * 2 + 0];
                float vy = acc[mf][nf][half_ * 2 + 1];
                int c = (nf << 3);
                if (bias) {
                    vx += bias[col0 + c];
                    vy += bias[col0 + c + 1];
                }
                if (OUTH) {
                    if (relu) { vx = fmaxf(vx, 0.f); vy = fmaxf(vy, 0.f); }
                    __half2 hv = __floats2half2_rn(vx, vy);
                    *(__half2*)((__half*)Cout + (size_t)row * N + col0 + c) = hv;
                } else {
                    if (res) {
                        const float* rp = res + (size_t)row * N + col0 + c;
                        float2 r2 = *(const float2*)rp;
                        vx += r2.x; vy += r2.y;
                    }
                    float2 v; v.x = vx; v.y = vy;
                    *(float2*)((float*)Cout + (size_t)row * N + col0 + c) = v;
                }
            }
        }
    }
}

// ---------------- embedding ----------------
__global__ void k_embed(const int* __restrict__ idx,
                        const float* __restrict__ tok,
                        const float* __restrict__ pos,
                        float* __restrict__ x)
{
    int m = blockIdx.x;
    int c = threadIdx.x * 4;
    int t = m & (T_SEQ - 1);
    int v = idx[m];
    float4 a = *(const float4*)(tok + (size_t)v * C_DIM + c);
    float4 p = *(const float4*)(pos + (size_t)t * C_DIM + c);
    a.x += p.x; a.y += p.y; a.z += p.z; a.w += p.w;
    *(float4*)(x + (size_t)m * C_DIM + c) = a;
}

// ---------------- layernorm: fp32 in -> fp16 out ----------------
__global__ void k_ln(const float* __restrict__ x,
                     const float* __restrict__ sc,
                     const float* __restrict__ bi,
                     __half* __restrict__ out)
{
    int m = blockIdx.x;
    int tid = threadIdx.x;                 // 256 threads
    int c = tid * 4;
    float4 v = *(const float4*)(x + (size_t)m * C_DIM + c);
    float s = v.x + v.y + v.z + v.w;
    float q = v.x*v.x + v.y*v.y + v.z*v.z + v.w*v.w;

    __shared__ float rs[8], rq[8];
#pragma unroll
    for (int o = 16; o > 0; o >>= 1) {
        s += __shfl_xor_sync(0xffffffffu, s, o);
        q += __shfl_xor_sync(0xffffffffu, q, o);
    }
    if ((tid & 31) == 0) { rs[tid >> 5] = s; rq[tid >> 5] = q; }
    __syncthreads();
    float sum = 0.f, sq = 0.f;
#pragma unroll
    for (int w = 0; w < 8; w++) { sum += rs[w]; sq += rq[w]; }

    float mu = sum * (1.0f / C_DIM);
    float var = sq * (1.0f / C_DIM) - mu * mu;
    float rstd = rsqrtf(var + 1e-5f);

    float4 svv = *(const float4*)(sc + c);
    float4 bvv = *(const float4*)(bi + c);
    __half2 p0 = __floats2half2_rn((v.x - mu) * rstd * svv.x + bvv.x,
                                   (v.y - mu) * rstd * svv.y + bvv.y);
    __half2 p1 = __floats2half2_rn((v.z - mu) * rstd * svv.z + bvv.z,
                                   (v.w - mu) * rstd * svv.w + bvv.w);
    uint2 st;
    st.x = *(uint32_t*)&p0;
    st.y = *(uint32_t*)&p1;
    *(uint2*)(out + (size_t)m * C_DIM + c) = st;
}

// ---------------- pack qkv weights ALL layers -> [L][3C, C] half ----------------
__global__ __launch_bounds__(256)
void k_packQKV(const float* __restrict__ Wq, const float* __restrict__ Wk,
               const float* __restrict__ Wv, __half* __restrict__ out)
{
    __shared__ float t[32][65];
    int b  = blockIdx.x;
    int l  = b / 1536;
    b -= l * 1536;
    int kb = b & 31;
    int hh = (b >> 5) & 15;
    int s  = b >> 9;
    const float* W = (s == 0) ? Wq : ((s == 1) ? Wk : Wv);
    const float* Wb = W + ((size_t)l * H_NUM + hh) * C_DIM * D_HEAD + (size_t)(kb << 5) * D_HEAD;
    int tid = threadIdx.x;
#pragma unroll
    for (int i = 0; i < 8; i++) {
        int idx = tid + (i << 8);
        int r = idx >> 6, d = idx & 63;
        t[r][d] = Wb[(size_t)r * D_HEAD + d];
    }
    __syncthreads();
    __half* outl = out + (size_t)l * 3 * C_DIM * C_DIM;
    int n0 = s * 1024 + hh * 64;
#pragma unroll
    for (int i = 0; i < 8; i++) {
        int idx = tid + (i << 8);
        int d = idx >> 5, kk = idx & 31;
        outl[(size_t)(n0 + d) * C_DIM + (kb << 5) + kk] = __float2half_rn(t[kk][d]);
    }
}

// ---------------- pure fp32 -> fp16 convert (layout preserved) ----------------
__global__ __launch_bounds__(256)
void k_cvt(const float* __restrict__ in, __half* __restrict__ out)
{
    size_t i = ((size_t)blockIdx.x * 256 + threadIdx.x) * 8;
    float4 a = *(const float4*)(in + i);
    float4 b = *(const float4*)(in + i + 4);
    __half2 h0 = __floats2half2_rn(a.x, a.y);
    __half2 h1 = __floats2half2_rn(a.z, a.w);
    __half2 h2 = __floats2half2_rn(b.x, b.y);
    __half2 h3 = __floats2half2_rn(b.z, b.w);
    uint4 st;
    st.x = *(uint32_t*)&h0; st.y = *(uint32_t*)&h1;
    st.z = *(uint32_t*)&h2; st.w = *(uint32_t*)&h3;
    *(uint4*)(out + i) = st;
}

// ============================================================
// Tensor-core causal flash attention.
// ============================================================
#define AT_PAD  72
#define AT_TILEB (64 * AT_PAD * 2)

__global__ __launch_bounds__(128)
void k_attn(const __half* __restrict__ qkvh, __half* __restrict__ outb)
{
    __shared__ __half Qs[64][AT_PAD];
    __shared__ __half Ks[2][64][AT_PAD];
    __shared__ __half Vs[2][64][AT_PAD];

    int qt = blockIdx.x;
    int b  = blockIdx.y >> 4;
    int hh = blockIdx.y & 15;
    int tid = threadIdx.x;
    int wid = tid >> 5, lane = tid & 31;

    const __half* qp = qkvh + ((size_t)(b * T_SEQ + qt * 64)) * 3072 + hh * 64;
    const __half* kp = qkvh + ((size_t)(b * T_SEQ)) * 3072 + 1024 + hh * 64;
    const __half* vp = kp + 1024;

    uint32_t sQ = smem_u32(Qs);
    uint32_t sK = smem_u32(Ks);
    uint32_t sV = smem_u32(Vs);

#pragma unroll
    for (int i = 0; i < 4; i++) {
        int id = tid + (i << 7);
        int r = id >> 3, c = (id & 7) << 3;
        uint32_t off = (uint32_t)(r * AT_PAD + c) << 1;
        cpa16(sQ + off, qp + (size_t)r * 3072 + c);
        cpa16(sK + off, kp + (size_t)r * 3072 + c);
        cpa16(sV + off, vp + (size_t)r * 3072 + c);
    }
    asm volatile("cp.async.commit_group;");

    uint32_t qf[4][4];
    float oa[8][4];
    float m0 = -1e30f, m1 = -1e30f, l0 = 0.f, l1 = 0.f;
#pragma unroll
    for (int i = 0; i < 8; i++) { oa[i][0] = oa[i][1] = oa[i][2] = oa[i][3] = 0.f; }

    for (int kt = 0; kt <= qt; kt++) {
        if (kt > 0) __syncthreads();
        if (kt < qt) {
            uint32_t st = (uint32_t)((kt + 1) & 1) * AT_TILEB;
#pragma unroll
            for (int i = 0; i < 4; i++) {
                int id = tid + (i << 7);
                int r = id >> 3, c = (id & 7) << 3;
                uint32_t off = (uint32_t)(r * AT_PAD + c) << 1;
                cpa16(sK + st + off, kp + (size_t)((kt + 1) * 64 + r) * 3072 + c);
                cpa16(sV + st + off, vp + (size_t)((kt + 1) * 64 + r) * 3072 + c);
            }
        }
        asm volatile("cp.async.commit_group;");
        asm volatile("cp.async.wait_group 1;");
        __syncthreads();

        if (kt == 0) {
            uint32_t rAq = (uint32_t)(wid << 4) + (lane & 7) + (((lane >> 3) & 1) << 3);
#pragma unroll
            for (int kc = 0; kc < 4; kc++) {
                uint32_t kAq = (((lane >> 4) & 1) << 3) + (kc << 4);
                ldsm4(qf[kc][0], qf[kc][1], qf[kc][2], qf[kc][3],
                      sQ + ((rAq * AT_PAD + kAq) << 1));
            }
        }

        uint32_t sKt = sK + (uint32_t)(kt & 1) * AT_TILEB;
        uint32_t sVt = sV + (uint32_t)(kt & 1) * AT_TILEB;

        float s[8][4];
#pragma unroll
        for (int i = 0; i < 8; i++) { s[i][0] = s[i][1] = s[i][2] = s[i][3] = 0.f; }
        uint32_t rBk = (lane & 7) + (((lane >> 4) & 1) << 3);
        uint32_t kBo = ((lane >> 3) & 1) << 3;
#pragma unroll
        for (int kc = 0; kc < 4; kc++) {
#pragma unroll
            for (int p = 0; p < 4; p++) {
                uint32_t b0, b1, b2, b3;
                ldsm4(b0, b1, b2, b3,
                      sKt + (((rBk + (uint32_t)(p << 4)) * AT_PAD + kBo + (kc << 4)) << 1));
                mma_f16(s[2*p][0], s[2*p][1], s[2*p][2], s[2*p][3],
                        qf[kc][0], qf[kc][1], qf[kc][2], qf[kc][3], b0, b1);
                mma_f16(s[2*p+1][0], s[2*p+1][1], s[2*p+1][2], s[2*p+1][3],
                        qf[kc][0], qf[kc][1], qf[kc][2], qf[kc][3], b2, b3);
            }
        }
#pragma unroll
        for (int i = 0; i < 8; i++) {
            s[i][0] *= 0.125f; s[i][1] *= 0.125f; s[i][2] *= 0.125f; s[i][3] *= 0.125f;
        }
        if (kt == qt) {
            int r0 = (wid << 4) + (lane >> 2);
#pragma unroll
            for (int nf = 0; nf < 8; nf++) {
                int c0 = (nf << 3) + ((lane & 3) << 1);
                if (c0     > r0)     s[nf][0] = -1e30f;
                if (c0 + 1 > r0)     s[nf][1] = -1e30f;
                if (c0     > r0 + 8) s[nf][2] = -1e30f;
                if (c0 + 1 > r0 + 8) s[nf][3] = -1e30f;
            }
        }

        float mx0 = s[0][0], mx1 = s[0][2];
#pragma unroll
        for (int nf = 0; nf < 8; nf++) {
            mx0 = fmaxf(mx0, fmaxf(s[nf][0], s[nf][1]));
            mx1 = fmaxf(mx1, fmaxf(s[nf][2], s[nf][3]));
        }
        mx0 = fmaxf(mx0, __shfl_xor_sync(0xffffffffu, mx0, 1));
        mx0 = fmaxf(mx0, __shfl_xor_sync(0xffffffffu, mx0, 2));
        mx1 = fmaxf(mx1, __shfl_xor_sync(0xffffffffu, mx1, 1));
        mx1 = fmaxf(mx1, __shfl_xor_sync(0xffffffffu, mx1, 2));
        float mn0 = fmaxf(m0, mx0), mn1 = fmaxf(m1, mx1);
        float cr0 = __expf(m0 - mn0), cr1 = __expf(m1 - mn1);
        float rs0 = 0.f, rs1 = 0.f;
        uint32_t pa[4][4];
#pragma unroll
        for (int nf = 0; nf < 8; nf++) {
            float p0 = __expf(s[nf][0] - mn0);
            float p1 = __expf(s[nf][1] - mn0);
            float p2 = __expf(s[nf][2] - mn1);
            float p3 = __expf(s[nf][3] - mn1);
            rs0 += p0 + p1; rs1 += p2 + p3;
            __half2 h01 = __floats2half2_rn(p0, p1);
            __half2 h23 = __floats2half2_rn(p2, p3);
            int kc = nf >> 1, hi = (nf & 1) << 1;
            pa[kc][hi]     = *(uint32_t*)&h01;
            pa[kc][hi + 1] = *(uint32_t*)&h23;
        }
        rs0 += __shfl_xor_sync(0xffffffffu, rs0, 1);
        rs0 += __shfl_xor_sync(0xffffffffu, rs0, 2);
        rs1 += __shfl_xor_sync(0xffffffffu, rs1, 1);
        rs1 += __shfl_xor_sync(0xffffffffu, rs1, 2);
        l0 = l0 * cr0 + rs0; l1 = l1 * cr1 + rs1;
        m0 = mn0; m1 = mn1;
#pragma unroll
        for (int i = 0; i < 8; i++) {
            oa[i][0] *= cr0; oa[i][1] *= cr0; oa[i][2] *= cr1; oa[i][3] *= cr1;
        }

        uint32_t rV = (lane & 7) + (((lane >> 3) & 1) << 3);
        uint32_t cV = ((lane >> 4) & 1) << 3;
#pragma unroll
        for (int kc = 0; kc < 4; kc++) {
#pragma unroll
            for (int p = 0; p < 4; p++) {
                uint32_t b0, b1, b2, b3;
                ldsm4t(b0, b1, b2, b3,
                       sVt + ((((uint32_t)(kc << 4) + rV) * AT_PAD + (uint32_t)(p << 4) + cV) << 1));
                mma_f16(oa[2*p][0], oa[2*p][1], oa[2*p][2], oa[2*p][3],
                        pa[kc][0], pa[kc][1], pa[kc][2], pa[kc][3], b0, b1);
                mma_f16(oa[2*p+1][0], oa[2*p+1][1], oa[2*p+1][2], oa[2*p+1][3],
                        pa[kc][0], pa[kc][1], pa[kc][2], pa[kc][3], b2, b3);
            }
        }
    }

    float i0 = 1.0f / l0, i1 = 1.0f / l1;
    int r0 = qt * 64 + (wid << 4) + (lane >> 2);
    __half* ob = outb + (size_t)(b * T_SEQ) * C_DIM + hh * 64;
#pragma unroll
    for (int nf = 0; nf < 8; nf++) {
        int c = (nf << 3) + ((lane & 3) << 1);
        __half2 h0 = __floats2half2_rn(oa[nf][0] * i0, oa[nf][1] * i0);
        __half2 h1 = __floats2half2_rn(oa[nf][2] * i1, oa[nf][3] * i1);
        *(__half2*)(ob + (size_t)r0 * C_DIM + c)       = h0;
        *(__half2*)(ob + (size_t)(r0 + 8) * C_DIM + c) = h1;
    }
}

// ---------------- smem sizes per instantiation (BK=64, 2-stage) ----------------
#define GSM_128_NK  ((128 * ROWH + 128 * ROWH) * 2 * 2)   // 73728
#define GSM_64_NK   ((64 * ROWH + 128 * ROWH) * 2 * 2)    // 55296
#define GSM_128_KN  ((128 * ROWH + 64 * ROWB) * 2 * 2)    // 71680
#define GSM_64_KN   ((64 * ROWH + 64 * ROWB) * 2 * 2)     // 53248

// ---------------- launcher ----------------
extern "C" void kernel_launch(void* const* d_in, const int* in_sizes, int n_in,
                              void* d_out, int out_size)
{
    const int*   idx    = (const int*)  d_in[0];
    const float* tok    = (const float*)d_in[1];
    const float* pos    = (const float*)d_in[2];
    const float* ln1_s  = (const float*)d_in[3];
    const float* ln1_b  = (const float*)d_in[4];
    const float* Wq     = (const float*)d_in[5];
    const float* Wk     = (const float*)d_in[6];
    const float* Wv     = (const float*)d_in[7];
    const float* Wo     = (const float*)d_in[8];
    const float* bo     = (const float*)d_in[9];
    const float* ln2_s  = (const float*)d_in[10];
    const float* ln2_b  = (const float*)d_in[11];
    const float* W1     = (const float*)d_in[12];
    const float* b1     = (const float*)d_in[13];
    const float* W2     = (const float*)d_in[14];
    const float* b2     = (const float*)d_in[15];
    const float* lnf_s  = (const float*)d_in[16];
    const float* lnf_b  = (const float*)d_in[17];
    float* out = (float*)d_out;

    float *x;
    __half *qkvh, *hh, *ffh, *wph, *woh, *w1h, *w2h, *tokh;
    cudaGetSymbolAddress((void**)&x,     g_x);
    cudaGetSymbolAddress((void**)&qkvh,  g_qkvh);
    cudaGetSymbolAddress((void**)&hh,    g_hh);
    cudaGetSymbolAddress((void**)&ffh,   g_ffh);
    cudaGetSymbolAddress((void**)&wph,   g_wph);
    cudaGetSymbolAddress((void**)&woh,   g_woh);
    cudaGetSymbolAddress((void**)&w1h,   g_w1h);
    cudaGetSymbolAddress((void**)&w2h,   g_w2h);
    cudaGetSymbolAddress((void**)&tokh,  g_tokh);

    cudaFuncSetAttribute(hgemm<64,1,1>,  cudaFuncAttributeMaxDynamicSharedMemorySize, GSM_64_NK);
    cudaFuncSetAttribute(hgemm<128,0,1>, cudaFuncAttributeMaxDynamicSharedMemorySize, GSM_128_NK);
    cudaFuncSetAttribute(hgemm<64,1,0>,  cudaFuncAttributeMaxDynamicSharedMemorySize, GSM_64_KN);
    cudaFuncSetAttribute(hgemm<64,0,0>,  cudaFuncAttributeMaxDynamicSharedMemorySize, GSM_64_KN);

    // ---- one-time per call: weight conversion ----
    k_cvt<<<(V_SZ * C_DIM) / 2048, 256>>>(tok, tokh);
    k_cvt<<<(L_NUM * C_DIM * C_DIM) / 2048, 256>>>(Wo, woh);
    k_cvt<<<(L_NUM * C_DIM * FF_DIM) / 2048, 256>>>(W1, w1h);
    k_cvt<<<(L_NUM * FF_DIM * C_DIM) / 2048, 256>>>(W2, w2h);
    k_packQKV<<<L_NUM * 1536, 256>>>(Wq, Wk, Wv, wph);
    k_embed<<<M_ROWS, 256>>>(idx, tok, pos, x);

    for (int l = 0; l < L_NUM; l++) {
        // LN1 -> half
        k_ln<<<M_ROWS, 256>>>(x, ln1_s + l * C_DIM, ln1_b + l * C_DIM, hh);
        // qkv = hh @ wph^T -> half   (MT=64: 768 CTAs @ 3/SM)
        hgemm<64,1,1><<<dim3(3072 / 128, M_ROWS / 64), 256, GSM_64_NK>>>(
            hh, wph + (size_t)l * 3 * C_DIM * C_DIM, qkvh, nullptr, nullptr, 3072, C_DIM, 0);
        // tensor-core flash attention -> hh
        k_attn<<<dim3(T_SEQ / 64, B_SZ * H_NUM), 128>>>(qkvh, hh);
        // x = x + hh @ Wo + bo   (Wo [K,N], MT=64)
        hgemm<64,0,0><<<dim3(C_DIM / 128, M_ROWS / 64), 256, GSM_64_KN>>>(
            hh, woh + (size_t)l * C_DIM * C_DIM, x, bo + l * C_DIM, x, C_DIM, C_DIM, 0);
        // LN2 -> half
        k_ln<<<M_ROWS, 256>>>(x, ln2_s + l * C_DIM, ln2_b + l * C_DIM, hh);
        // ffh = relu(hh @ W1 + b1) -> half  (W1 [K,N], MT=64: 1024 CTAs @ 3/SM)
        hgemm<64,1,0><<<dim3(FF_DIM / 128, M_ROWS / 64), 256, GSM_64_KN>>>(
            hh, w1h + (size_t)l * C_DIM * FF_DIM, ffh, b1 + l * FF_DIM, nullptr, FF_DIM, C_DIM, 1);
        // x = x + ffh @ W2 + b2  (W2 [K,N], MT=64)
        hgemm<64,0,0><<<dim3(C_DIM / 128, M_ROWS / 64), 256, GSM_64_KN>>>(
            ffh, w2h + (size_t)l * FF_DIM * C_DIM, x, b2 + l * C_DIM, x, C_DIM, FF_DIM, 0);
    }

    // final LN + tied-embedding logits (tok [V,K] -> MT=128 TRB=1, many waves)
    k_ln<<<M_ROWS, 256>>>(x, lnf_s, lnf_b, hh);
    hgemm<128,0,1><<<dim3(V_SZ / 128, M_ROWS / 128), 256, GSM_128_NK>>>(
        hh, tokh, out, nullptr, nullptr, V_SZ, C_DIM, 0);
}

// round 16
// speedup vs baseline: 1.0365x; 1.0328x over previous
#include <cuda_runtime.h>
#include <cuda_fp16.h>
#include <cstdint>
#include <math.h>

// ---------------- model constants ----------------
#define C_DIM   1024
#define H_NUM   16
#define D_HEAD  64
#define L_NUM   8
#define T_SEQ   1024
#define B_SZ    2
#define M_ROWS  (B_SZ * T_SEQ)      // 2048
#define FF_DIM  4096
#define V_SZ    32000

// ---------------- device scratch ----------------
__device__ __align__(256) float  g_x   [M_ROWS * C_DIM];            // residual (fp32)
__device__ __align__(256) __half g_qkvh[M_ROWS * 3 * C_DIM];        // qkv (half)
__device__ __align__(256) __half g_hh  [M_ROWS * C_DIM];            // LN out / attn out
__device__ __align__(256) __half g_ffh [M_ROWS * FF_DIM];           // relu FF out
__device__ __align__(256) __half g_wph [L_NUM * 3 * C_DIM * C_DIM]; // qkv W [N,K] all layers
__device__ __align__(256) __half g_woh [L_NUM * C_DIM * C_DIM];     // Wo half [K,N]
__device__ __align__(256) __half g_w1h [L_NUM * C_DIM * FF_DIM];    // W1 half [K,N]
__device__ __align__(256) __half g_w2h [L_NUM * FF_DIM * C_DIM];    // W2 half [K,N]
__device__ __align__(256) __half g_tokh[V_SZ * C_DIM];              // tok [V,K]

// ============================================================
// helpers
// ============================================================
__device__ __forceinline__ uint32_t smem_u32(const void* p) {
    uint32_t a;
    asm("{ .reg .u64 t; cvta.to.shared.u64 t, %1; cvt.u32.u64 %0, t; }" : "=r"(a) : "l"(p));
    return a;
}
__device__ __forceinline__ void cpa16(uint32_t dst, const void* src) {
    asm volatile("cp.async.cg.shared.global [%0], [%1], 16;" :: "r"(dst), "l"(src));
}
__device__ __forceinline__ void ldsm4(uint32_t& r0, uint32_t& r1, uint32_t& r2, uint32_t& r3,
                                      uint32_t a) {
    asm volatile("ldmatrix.sync.aligned.m8n8.x4.shared.b16 {%0,%1,%2,%3}, [%4];"
        : "=r"(r0), "=r"(r1), "=r"(r2), "=r"(r3) : "r"(a));
}
__device__ __forceinline__ void ldsm4t(uint32_t& r0, uint32_t& r1, uint32_t& r2, uint32_t& r3,
                                       uint32_t a) {
    asm volatile("ldmatrix.sync.aligned.m8n8.x4.trans.shared.b16 {%0,%1,%2,%3}, [%4];"
        : "=r"(r0), "=r"(r1), "=r"(r2), "=r"(r3) : "r"(a));
}
__device__ __forceinline__ void mma_f16(float& c0, float& c1, float& c2, float& c3,
                                        uint32_t a0, uint32_t a1, uint32_t a2, uint32_t a3,
                                        uint32_t b0, uint32_t b1) {
    asm volatile("mma.sync.aligned.m16n8k16.row.col.f32.f16.f16.f32 "
        "{%0,%1,%2,%3}, {%4,%5,%6,%7}, {%8,%9}, {%0,%1,%2,%3};"
        : "+f"(c0), "+f"(c1), "+f"(c2), "+f"(c3)
        : "r"(a0), "r"(a1), "r"(a2), "r"(a3), "r"(b0), "r"(b1));
}

// ============================================================
// FP16 mma.sync GEMM (round-9 proven config): BK=64, 2-stage cp.async.
//   MT: CTA M-tile (128 or 64); N-tile 128. 256 threads, 8 warps (2x4).
//   TRB=1: B stored [N,K]; TRB=0: B stored [K,N] via ldsm trans.
//   OUTH=1: half out (+bias)(+relu). OUTH=0: fp32 out (+bias)(+res).
// ============================================================
#define ROWH  72        // A / B-NK row pitch (64 + 8 pad halves)
#define ROWB  136       // B-KN row pitch (128 + 8 pad halves)

template<int MT, int OUTH, int TRB>
__global__ __launch_bounds__(256, MT == 64 ? 3 : 2)
void hgemm(const __half* __restrict__ A, const __half* __restrict__ B,
           void* __restrict__ Cout, const float* __restrict__ bias,
           const float* __restrict__ res, int N, int K, int relu)
{
    constexpr int MF      = MT / 32;
    constexpr int A_TILE  = MT * ROWH;
    constexpr int B_TILE  = TRB ? 128 * ROWH : 64 * ROWB;
    constexpr int STAGE_B = (A_TILE + B_TILE) * 2;

    extern __shared__ __half smh[];
    uint32_t sbase = smem_u32(smh);
    int tid  = threadIdx.x;
    int wid  = tid >> 5;
    int lane = tid & 31;
    int wm   = wid >> 2;
    int wn   = wid & 3;
    int bm = blockIdx.y * MT;
    int bn = blockIdx.x << 7;

    const __half* Ag = A + (size_t)bm * K;
    int NC = K >> 6;

    float acc[MF][4][4];
#pragma unroll
    for (int mf = 0; mf < MF; mf++)
#pragma unroll
        for (int nf = 0; nf < 4; nf++)
#pragma unroll
            for (int k = 0; k < 4; k++) acc[mf][nf][k] = 0.f;

    auto load_tile = [&](int ch, int stage) {
        int k0 = ch << 6;
        uint32_t so = sbase + (uint32_t)stage * STAGE_B;
        uint32_t bo = so + (uint32_t)A_TILE * 2u;
#pragma unroll
        for (int i = 0; i < MT / 32; i++) {
            int id = tid + (i << 8);
            int r = id >> 3, c = (id & 7) << 3;
            cpa16(so + ((uint32_t)(r * ROWH + c) << 1), Ag + (size_t)r * K + k0 + c);
        }
        if (TRB) {
            const __half* Bg = B + (size_t)bn * K;
#pragma unroll
            for (int i = 0; i < 4; i++) {
                int id = tid + (i << 8);
                int r = id >> 3, c = (id & 7) << 3;
                cpa16(bo + ((uint32_t)(r * ROWH + c) << 1), Bg + (size_t)r * K + k0 + c);
            }
        } else {
#pragma unroll
            for (int i = 0; i < 4; i++) {
                int id = tid + (i << 8);
                int r = id >> 4, c = (id & 15) << 3;
                cpa16(bo + ((uint32_t)(r * ROWB + c) << 1),
                      B + (size_t)(k0 + r) * N + bn + c);
            }
        }
    };

    load_tile(0, 0);
    asm volatile("cp.async.commit_group;");

    uint32_t rA = (uint32_t)(wm * (MT / 2)) + (lane & 7) + (((lane >> 3) & 1) << 3);
    uint32_t kA = ((lane >> 4) & 1) << 3;
    uint32_t rB = (uint32_t)(wn << 5) + (lane & 7) + (((lane >> 4) & 1) << 3);
    uint32_t kB = ((lane >> 3) & 1) << 3;
    uint32_t rBt = (lane & 7) + (((lane >> 3) & 1) << 3);
    uint32_t cBt = (uint32_t)(wn << 5) + (((lane >> 4) & 1) << 3);

    for (int ch = 0; ch < NC; ch++) {
        if (ch > 0) __syncthreads();
        if (ch + 1 < NC) load_tile(ch + 1, (ch + 1) & 1);
        asm volatile("cp.async.commit_group;");
        asm volatile("cp.async.wait_group 1;");
        __syncthreads();

        uint32_t sA = sbase + (uint32_t)(ch & 1) * STAGE_B;
        uint32_t sB = sA + (uint32_t)A_TILE * 2u;
#pragma unroll
        for (int ks = 0; ks < 4; ks++) {
            uint32_t af[MF][4], bf[4][2];
            uint32_t kofs = (uint32_t)(ks << 4);
#pragma unroll
            for (int mf = 0; mf < MF; mf++) {
                uint32_t a = sA + (((rA + (uint32_t)(mf << 4)) * ROWH + kA + kofs) << 1);
                ldsm4(af[mf][0], af[mf][1], af[mf][2], af[mf][3], a);
            }
            if (TRB) {
#pragma unroll
                for (int p = 0; p < 2; p++) {
                    uint32_t a = sB + (((rB + (uint32_t)(p << 4)) * ROWH + kB + kofs) << 1);
                    ldsm4(bf[2 * p][0], bf[2 * p][1], bf[2 * p + 1][0], bf[2 * p + 1][1], a);
                }
            } else {
#pragma unroll
                for (int p = 0; p < 2; p++) {
                    uint32_t a = sB + (((kofs + rBt) * ROWB + cBt + (uint32_t)(p << 4)) << 1);
                    ldsm4t(bf[2 * p][0], bf[2 * p][1], bf[2 * p + 1][0], bf[2 * p + 1][1], a);
                }
            }
#pragma unroll
            for (int mf = 0; mf < MF; mf++)
#pragma unroll
                for (int nf = 0; nf < 4; nf++)
                    mma_f16(acc[mf][nf][0], acc[mf][nf][1], acc[mf][nf][2], acc[mf][nf][3],
                            af[mf][0], af[mf][1], af[mf][2], af[mf][3],
                            bf[nf][0], bf[nf][1]);
        }
    }

    // ---- epilogue ----
    int row0 = bm + wm * (MT / 2) + (lane >> 2);
    int col0 = bn + (wn << 5) + ((lane & 3) << 1);
#pragma unroll
    for (int mf = 0; mf < MF; mf++) {
#pragma unroll
        for (int half_ = 0; half_ < 2; half_++) {
            int row = row0 + (mf << 4) + half_ * 8;
#pragma unroll
            for (int nf = 0; nf < 4; nf++) {
                float vx = acc[mf][nf][half_ * 2 + 0];
                float vy = acc[mf][nf][half_ * 2 + 1];
                int c = (nf << 3);
                if (bias) {
                    vx += bias[col0 + c];
                    vy += bias[col0 + c + 1];
                }
                if (OUTH) {
                    if (relu) { vx = fmaxf(vx, 0.f); vy = fmaxf(vy, 0.f); }
                    __half2 hv = __floats2half2_rn(vx, vy);
                    *(__half2*)((__half*)Cout + (size_t)row * N + col0 + c) = hv;
                } else {
                    if (res) {
                        const float* rp = res + (size_t)row * N + col0 + c;
                        float2 r2 = *(const float2*)rp;
                        vx += r2.x; vy += r2.y;
                    }
                    float2 v; v.x = vx; v.y = vy;
                    *(float2*)((float*)Cout + (size_t)row * N + col0 + c) = v;
                }
            }
        }
    }
}

// ---------------- embedding ----------------
__global__ void k_embed(const int* __restrict__ idx,
                        const float* __restrict__ tok,
                        const float* __restrict__ pos,
                        float* __restrict__ x)
{
    int m = blockIdx.x;
    int c = threadIdx.x * 4;
    int t = m & (T_SEQ - 1);
    int v = idx[m];
    float4 a = *(const float4*)(tok + (size_t)v * C_DIM + c);
    float4 p = *(const float4*)(pos + (size_t)t * C_DIM + c);
    a.x += p.x; a.y += p.y; a.z += p.z; a.w += p.w;
    *(float4*)(x + (size_t)m * C_DIM + c) = a;
}

// ---------------- layernorm: fp32 in -> fp16 out ----------------
__global__ void k_ln(const float* __restrict__ x,
                     const float* __restrict__ sc,
                     const float* __restrict__ bi,
                     __half* __restrict__ out)
{
    int m = blockIdx.x;
    int tid = threadIdx.x;                 // 256 threads
    int c = tid * 4;
    float4 v = *(const float4*)(x + (size_t)m * C_DIM + c);
    float s = v.x + v.y + v.z + v.w;
    float q = v.x*v.x + v.y*v.y + v.z*v.z + v.w*v.w;

    __shared__ float rs[8], rq[8];
#pragma unroll
    for (int o = 16; o > 0; o >>= 1) {
        s += __shfl_xor_sync(0xffffffffu, s, o);
        q += __shfl_xor_sync(0xffffffffu, q, o);
    }
    if ((tid & 31) == 0) { rs[tid >> 5] = s; rq[tid >> 5] = q; }
    __syncthreads();
    float sum = 0.f, sq = 0.f;
#pragma unroll
    for (int w = 0; w < 8; w++) { sum += rs[w]; sq += rq[w]; }

    float mu = sum * (1.0f / C_DIM);
    float var = sq * (1.0f / C_DIM) - mu * mu;
    float rstd = rsqrtf(var + 1e-5f);

    float4 svv = *(const float4*)(sc + c);
    float4 bvv = *(const float4*)(bi + c);
    __half2 p0 = __floats2half2_rn((v.x - mu) * rstd * svv.x + bvv.x,
                                   (v.y - mu) * rstd * svv.y + bvv.y);
    __half2 p1 = __floats2half2_rn((v.z - mu) * rstd * svv.z + bvv.z,
                                   (v.w - mu) * rstd * svv.w + bvv.w);
    uint2 st;
    st.x = *(uint32_t*)&p0;
    st.y = *(uint32_t*)&p1;
    *(uint2*)(out + (size_t)m * C_DIM + c) = st;
}

// ---------------- pack qkv weights ALL layers -> [L][3C, C] half ----------------
__global__ __launch_bounds__(256)
void k_packQKV(const float* __restrict__ Wq, const float* __restrict__ Wk,
               const float* __restrict__ Wv, __half* __restrict__ out)
{
    __shared__ float t[32][65];
    int b  = blockIdx.x;
    int l  = b / 1536;
    b -= l * 1536;
    int kb = b & 31;
    int hh = (b >> 5) & 15;
    int s  = b >> 9;
    const float* W = (s == 0) ? Wq : ((s == 1) ? Wk : Wv);
    const float* Wb = W + ((size_t)l * H_NUM + hh) * C_DIM * D_HEAD + (size_t)(kb << 5) * D_HEAD;
    int tid = threadIdx.x;
#pragma unroll
    for (int i = 0; i < 8; i++) {
        int idx = tid + (i << 8);
        int r = idx >> 6, d = idx & 63;
        t[r][d] = Wb[(size_t)r * D_HEAD + d];
    }
    __syncthreads();
    __half* outl = out + (size_t)l * 3 * C_DIM * C_DIM;
    int n0 = s * 1024 + hh * 64;
#pragma unroll
    for (int i = 0; i < 8; i++) {
        int idx = tid + (i << 8);
        int d = idx >> 5, kk = idx & 31;
        outl[(size_t)(n0 + d) * C_DIM + (kb << 5) + kk] = __float2half_rn(t[kk][d]);
    }
}

// ---------------- pure fp32 -> fp16 convert (layout preserved) ----------------
__global__ __launch_bounds__(256)
void k_cvt(const float* __restrict__ in, __half* __restrict__ out)
{
    size_t i = ((size_t)blockIdx.x * 256 + threadIdx.x) * 8;
    float4 a = *(const float4*)(in + i);
    float4 b = *(const float4*)(in + i + 4);
    __half2 h0 = __floats2half2_rn(a.x, a.y);
    __half2 h1 = __floats2half2_rn(a.z, a.w);
    __half2 h2 = __floats2half2_rn(b.x, b.y);
    __half2 h3 = __floats2half2_rn(b.z, b.w);
    uint4 st;
    st.x = *(uint32_t*)&h0; st.y = *(uint32_t*)&h1;
    st.z = *(uint32_t*)&h2; st.w = *(uint32_t*)&h3;
    *(uint4*)(out + i) = st;
}

// ============================================================
// Tensor-core causal flash attention — BALANCED pairing.
// grid (8, 32): CTA handles query tiles qtp and 15-qtp sequentially
// -> every CTA does exactly 17 K-tile iterations (was 1..16).
// ============================================================
#define AT_PAD  72
#define AT_TILEB (64 * AT_PAD * 2)

__global__ __launch_bounds__(128)
void k_attn(const __half* __restrict__ qkvh, __half* __restrict__ outb)
{
    __shared__ __half Qs[64][AT_PAD];
    __shared__ __half Ks[2][64][AT_PAD];
    __shared__ __half Vs[2][64][AT_PAD];

    int qtp = blockIdx.x;           // 0..7
    int b   = blockIdx.y >> 4;
    int hh  = blockIdx.y & 15;
    int tid = threadIdx.x;
    int wid = tid >> 5, lane = tid & 31;

    const __half* kp = qkvh + ((size_t)(b * T_SEQ)) * 3072 + 1024 + hh * 64;
    const __half* vp = kp + 1024;

    uint32_t sQ = smem_u32(Qs);
    uint32_t sK = smem_u32(Ks);
    uint32_t sV = smem_u32(Vs);

    for (int phase = 0; phase < 2; phase++) {
        int qt = (phase == 0) ? qtp : (15 - qtp);
        const __half* qp = qkvh + ((size_t)(b * T_SEQ + qt * 64)) * 3072 + hh * 64;

        // prologue: Q + K0 + V0
#pragma unroll
        for (int i = 0; i < 4; i++) {
            int id = tid + (i << 7);
            int r = id >> 3, c = (id & 7) << 3;
            uint32_t off = (uint32_t)(r * AT_PAD + c) << 1;
            cpa16(sQ + off, qp + (size_t)r * 3072 + c);
            cpa16(sK + off, kp + (size_t)r * 3072 + c);
            cpa16(sV + off, vp + (size_t)r * 3072 + c);
        }
        asm volatile("cp.async.commit_group;");

        uint32_t qf[4][4];
        float oa[8][4];
        float m0 = -1e30f, m1 = -1e30f, l0 = 0.f, l1 = 0.f;
#pragma unroll
        for (int i = 0; i < 8; i++) { oa[i][0] = oa[i][1] = oa[i][2] = oa[i][3] = 0.f; }

        for (int kt = 0; kt <= qt; kt++) {
            if (kt > 0) __syncthreads();
            if (kt < qt) {
                uint32_t st = (uint32_t)((kt + 1) & 1) * AT_TILEB;
#pragma unroll
                for (int i = 0; i < 4; i++) {
                    int id = tid + (i << 7);
                    int r = id >> 3, c = (id & 7) << 3;
                    uint32_t off = (uint32_t)(r * AT_PAD + c) << 1;
                    cpa16(sK + st + off, kp + (size_t)((kt + 1) * 64 + r) * 3072 + c);
                    cpa16(sV + st + off, vp + (size_t)((kt + 1) * 64 + r) * 3072 + c);
                }
            }
            asm volatile("cp.async.commit_group;");
            asm volatile("cp.async.wait_group 1;");
            __syncthreads();

            if (kt == 0) {
                uint32_t rAq = (uint32_t)(wid << 4) + (lane & 7) + (((lane >> 3) & 1) << 3);
#pragma unroll
                for (int kc = 0; kc < 4; kc++) {
                    uint32_t kAq = (((lane >> 4) & 1) << 3) + (kc << 4);
                    ldsm4(qf[kc][0], qf[kc][1], qf[kc][2], qf[kc][3],
                          sQ + ((rAq * AT_PAD + kAq) << 1));
                }
            }

            uint32_t sKt = sK + (uint32_t)(kt & 1) * AT_TILEB;
            uint32_t sVt = sV + (uint32_t)(kt & 1) * AT_TILEB;

            float s[8][4];
#pragma unroll
            for (int i = 0; i < 8; i++) { s[i][0] = s[i][1] = s[i][2] = s[i][3] = 0.f; }
            uint32_t rBk = (lane & 7) + (((lane >> 4) & 1) << 3);
            uint32_t kBo = ((lane >> 3) & 1) << 3;
#pragma unroll
            for (int kc = 0; kc < 4; kc++) {
#pragma unroll
                for (int p = 0; p < 4; p++) {
                    uint32_t b0, b1, b2, b3;
                    ldsm4(b0, b1, b2, b3,
                          sKt + (((rBk + (uint32_t)(p << 4)) * AT_PAD + kBo + (kc << 4)) << 1));
                    mma_f16(s[2*p][0], s[2*p][1], s[2*p][2], s[2*p][3],
                            qf[kc][0], qf[kc][1], qf[kc][2], qf[kc][3], b0, b1);
                    mma_f16(s[2*p+1][0], s[2*p+1][1], s[2*p+1][2], s[2*p+1][3],
                            qf[kc][0], qf[kc][1], qf[kc][2], qf[kc][3], b2, b3);
                }
            }
#pragma unroll
            for (int i = 0; i < 8; i++) {
                s[i][0] *= 0.125f; s[i][1] *= 0.125f; s[i][2] *= 0.125f; s[i][3] *= 0.125f;
            }
            if (kt == qt) {
                int r0 = (wid << 4) + (lane >> 2);
#pragma unroll
                for (int nf = 0; nf < 8; nf++) {
                    int c0 = (nf << 3) + ((lane & 3) << 1);
                    if (c0     > r0)     s[nf][0] = -1e30f;
                    if (c0 + 1 > r0)     s[nf][1] = -1e30f;
                    if (c0     > r0 + 8) s[nf][2] = -1e30f;
                    if (c0 + 1 > r0 + 8) s[nf][3] = -1e30f;
                }
            }

            float mx0 = s[0][0], mx1 = s[0][2];
#pragma unroll
            for (int nf = 0; nf < 8; nf++) {
                mx0 = fmaxf(mx0, fmaxf(s[nf][0], s[nf][1]));
                mx1 = fmaxf(mx1, fmaxf(s[nf][2], s[nf][3]));
            }
            mx0 = fmaxf(mx0, __shfl_xor_sync(0xffffffffu, mx0, 1));
            mx0 = fmaxf(mx0, __shfl_xor_sync(0xffffffffu, mx0, 2));
            mx1 = fmaxf(mx1, __shfl_xor_sync(0xffffffffu, mx1, 1));
            mx1 = fmaxf(mx1, __shfl_xor_sync(0xffffffffu, mx1, 2));
            float mn0 = fmaxf(m0, mx0), mn1 = fmaxf(m1, mx1);
            float cr0 = __expf(m0 - mn0), cr1 = __expf(m1 - mn1);
            float rs0 = 0.f, rs1 = 0.f;
            uint32_t pa[4][4];
#pragma unroll
            for (int nf = 0; nf < 8; nf++) {
                float p0 = __expf(s[nf][0] - mn0);
                float p1 = __expf(s[nf][1] - mn0);
                float p2 = __expf(s[nf][2] - mn1);
                float p3 = __expf(s[nf][3] - mn1);
                rs0 += p0 + p1; rs1 += p2 + p3;
                __half2 h01 = __floats2half2_rn(p0, p1);
                __half2 h23 = __floats2half2_rn(p2, p3);
                int kc = nf >> 1, hi = (nf & 1) << 1;
                pa[kc][hi]     = *(uint32_t*)&h01;
                pa[kc][hi + 1] = *(uint32_t*)&h23;
            }
            rs0 += __shfl_xor_sync(0xffffffffu, rs0, 1);
            rs0 += __shfl_xor_sync(0xffffffffu, rs0, 2);
            rs1 += __shfl_xor_sync(0xffffffffu, rs1, 1);
            rs1 += __shfl_xor_sync(0xffffffffu, rs1, 2);
            l0 = l0 * cr0 + rs0; l1 = l1 * cr1 + rs1;
            m0 = mn0; m1 = mn1;
#pragma unroll
            for (int i = 0; i < 8; i++) {
                oa[i][0] *= cr0; oa[i][1] *= cr0; oa[i][2] *= cr1; oa[i][3] *= cr1;
            }

            uint32_t rV = (lane & 7) + (((lane >> 3) & 1) << 3);
            uint32_t cV = ((lane >> 4) & 1) << 3;
#pragma unroll
            for (int kc = 0; kc < 4; kc++) {
#pragma unroll
                for (int p = 0; p < 4; p++) {
                    uint32_t b0, b1, b2, b3;
                    ldsm4t(b0, b1, b2, b3,
                           sVt + ((((uint32_t)(kc << 4) + rV) * AT_PAD + (uint32_t)(p << 4) + cV) << 1));
                    mma_f16(oa[2*p][0], oa[2*p][1], oa[2*p][2], oa[2*p][3],
                            pa[kc][0], pa[kc][1], pa[kc][2], pa[kc][3], b0, b1);
                    mma_f16(oa[2*p+1][0], oa[2*p+1][1], oa[2*p+1][2], oa[2*p+1][3],
                            pa[kc][0], pa[kc][1], pa[kc][2], pa[kc][3], b2, b3);
                }
            }
        }

        // ---- phase epilogue ----
        float i0 = 1.0f / l0, i1 = 1.0f / l1;
        int r0 = qt * 64 + (wid << 4) + (lane >> 2);
        __half* ob = outb + (size_t)(b * T_SEQ) * C_DIM + hh * 64;
#pragma unroll
        for (int nf = 0; nf < 8; nf++) {
            int c = (nf << 3) + ((lane & 3) << 1);
            __half2 h0 = __floats2half2_rn(oa[nf][0] * i0, oa[nf][1] * i0);
            __half2 h1 = __floats2half2_rn(oa[nf][2] * i1, oa[nf][3] * i1);
            *(__half2*)(ob + (size_t)r0 * C_DIM + c)       = h0;
            *(__half2*)(ob + (size_t)(r0 + 8) * C_DIM + c) = h1;
        }

        // all warps done reading smem of this phase before next phase overwrites
        __syncthreads();
    }
}

// ---------------- smem sizes per instantiation (BK=64, 2-stage) ----------------
#define GSM_128_NK  ((128 * ROWH + 128 * ROWH) * 2 * 2)   // 73728
#define GSM_128_KN  ((128 * ROWH + 64 * ROWB) * 2 * 2)    // 71680
#define GSM_64_KN   ((64 * ROWH + 64 * ROWB) * 2 * 2)     // 53248

// ---------------- launcher ----------------
extern "C" void kernel_launch(void* const* d_in, const int* in_sizes, int n_in,
                              void* d_out, int out_size)
{
    const int*   idx    = (const int*)  d_in[0];
    const float* tok    = (const float*)d_in[1];
    const float* pos    = (const float*)d_in[2];
    const float* ln1_s  = (const float*)d_in[3];
    const float* ln1_b  = (const float*)d_in[4];
    const float* Wq     = (const float*)d_in[5];
    const float* Wk     = (const float*)d_in[6];
    const float* Wv     = (const float*)d_in[7];
    const float* Wo     = (const float*)d_in[8];
    const float* bo     = (const float*)d_in[9];
    const float* ln2_s  = (const float*)d_in[10];
    const float* ln2_b  = (const float*)d_in[11];
    const float* W1     = (const float*)d_in[12];
    const float* b1     = (const float*)d_in[13];
    const float* W2     = (const float*)d_in[14];
    const float* b2     = (const float*)d_in[15];
    const float* lnf_s  = (const float*)d_in[16];
    const float* lnf_b  = (const float*)d_in[17];
    float* out = (float*)d_out;

    float *x;
    __half *qkvh, *hh, *ffh, *wph, *woh, *w1h, *w2h, *tokh;
    cudaGetSymbolAddress((void**)&x,     g_x);
    cudaGetSymbolAddress((void**)&qkvh,  g_qkvh);
    cudaGetSymbolAddress((void**)&hh,    g_hh);
    cudaGetSymbolAddress((void**)&ffh,   g_ffh);
    cudaGetSymbolAddress((void**)&wph,   g_wph);
    cudaGetSymbolAddress((void**)&woh,   g_woh);
    cudaGetSymbolAddress((void**)&w1h,   g_w1h);
    cudaGetSymbolAddress((void**)&w2h,   g_w2h);
    cudaGetSymbolAddress((void**)&tokh,  g_tokh);

    cudaFuncSetAttribute(hgemm<128,1,1>, cudaFuncAttributeMaxDynamicSharedMemorySize, GSM_128_NK);
    cudaFuncSetAttribute(hgemm<128,0,1>, cudaFuncAttributeMaxDynamicSharedMemorySize, GSM_128_NK);
    cudaFuncSetAttribute(hgemm<128,1,0>, cudaFuncAttributeMaxDynamicSharedMemorySize, GSM_128_KN);
    cudaFuncSetAttribute(hgemm<64,0,0>,  cudaFuncAttributeMaxDynamicSharedMemorySize, GSM_64_KN);

    // ---- one-time per call: weight conversion ----
    k_cvt<<<(V_SZ * C_DIM) / 2048, 256>>>(tok, tokh);
    k_cvt<<<(L_NUM * C_DIM * C_DIM) / 2048, 256>>>(Wo, woh);
    k_cvt<<<(L_NUM * C_DIM * FF_DIM) / 2048, 256>>>(W1, w1h);
    k_cvt<<<(L_NUM * FF_DIM * C_DIM) / 2048, 256>>>(W2, w2h);
    k_packQKV<<<L_NUM * 1536, 256>>>(Wq, Wk, Wv, wph);
    k_embed<<<M_ROWS, 256>>>(idx, tok, pos, x);

    for (int l = 0; l < L_NUM; l++) {
        // LN1 -> half
        k_ln<<<M_ROWS, 256>>>(x, ln1_s + l * C_DIM, ln1_b + l * C_DIM, hh);
        // qkv = hh @ wph^T -> half  (round-9 config: MT=128)
        hgemm<128,1,1><<<dim3(3072 / 128, M_ROWS / 128), 256, GSM_128_NK>>>(
            hh, wph + (size_t)l * 3 * C_DIM * C_DIM, qkvh, nullptr, nullptr, 3072, C_DIM, 0);
        // balanced tensor-core flash attention -> hh
        k_attn<<<dim3(T_SEQ / 128, B_SZ * H_NUM), 128>>>(qkvh, hh);
        // x = x + hh @ Wo + bo   (Wo [K,N], MT=64)
        hgemm<64,0,0><<<dim3(C_DIM / 128, M_ROWS / 64), 256, GSM_64_KN>>>(
            hh, woh + (size_t)l * C_DIM * C_DIM, x, bo + l * C_DIM, x, C_DIM, C_DIM, 0);
        // LN2 -> half
        k_ln<<<M_ROWS, 256>>>(x, ln2_s + l * C_DIM, ln2_b + l * C_DIM, hh);
        // ffh = relu(hh @ W1 + b1) -> half  (W1 [K,N], MT=128)
        hgemm<128,1,0><<<dim3(FF_DIM / 128, M_ROWS / 128), 256, GSM_128_KN>>>(
            hh, w1h + (size_t)l * C_DIM * FF_DIM, ffh, b1 + l * FF_DIM, nullptr, FF_DIM, C_DIM, 1);
        // x = x + ffh @ W2 + b2  (W2 [K,N], MT=64)
        hgemm<64,0,0><<<dim3(C_DIM / 128, M_ROWS / 64), 256, GSM_64_KN>>>(
            ffh, w2h + (size_t)l * FF_DIM * C_DIM, x, b2 + l * C_DIM, x, C_DIM, FF_DIM, 0);
    }

    // final LN + tied-embedding logits (tok [V,K] -> MT=128 TRB=1)
    k_ln<<<M_ROWS, 256>>>(x, lnf_s, lnf_b, hh);
    hgemm<128,0,1><<<dim3(V_SZ / 128, M_ROWS / 128), 256, GSM_128_NK>>>(
        hh, tokh, out, nullptr, nullptr, V_SZ, C_DIM, 0);
}

// round 17
// speedup vs baseline: 1.0437x; 1.0070x over previous
#include <cuda_runtime.h>
#include <cuda_fp16.h>
#include <cstdint>
#include <math.h>

// ---------------- model constants ----------------
#define C_DIM   1024
#define H_NUM   16
#define D_HEAD  64
#define L_NUM   8
#define T_SEQ   1024
#define B_SZ    2
#define M_ROWS  (B_SZ * T_SEQ)      // 2048
#define FF_DIM  4096
#define V_SZ    32000

// ---------------- device scratch ----------------
__device__ __align__(256) float  g_x   [M_ROWS * C_DIM];            // residual (fp32)
__device__ __align__(256) __half g_qkvh[M_ROWS * 3 * C_DIM];        // qkv (half)
__device__ __align__(256) __half g_hh  [M_ROWS * C_DIM];            // LN out / attn out
__device__ __align__(256) __half g_ffh [M_ROWS * FF_DIM];           // relu FF out
__device__ __align__(256) __half g_wph [L_NUM * 3 * C_DIM * C_DIM]; // qkv W [N,K] all layers
__device__ __align__(256) __half g_woh [L_NUM * C_DIM * C_DIM];     // Wo half [K,N]
__device__ __align__(256) __half g_w1h [L_NUM * C_DIM * FF_DIM];    // W1 half [K,N]
__device__ __align__(256) __half g_w2h [L_NUM * FF_DIM * C_DIM];    // W2 half [K,N]
__device__ __align__(256) __half g_tokh[V_SZ * C_DIM];              // tok [V,K]

// ============================================================
// helpers
// ============================================================
__device__ __forceinline__ uint32_t smem_u32(const void* p) {
    uint32_t a;
    asm("{ .reg .u64 t; cvta.to.shared.u64 t, %1; cvt.u32.u64 %0, t; }" : "=r"(a) : "l"(p));
    return a;
}
__device__ __forceinline__ void cpa16(uint32_t dst, const void* src) {
    asm volatile("cp.async.cg.shared.global [%0], [%1], 16;" :: "r"(dst), "l"(src));
}
__device__ __forceinline__ void ldsm4(uint32_t& r0, uint32_t& r1, uint32_t& r2, uint32_t& r3,
                                      uint32_t a) {
    asm volatile("ldmatrix.sync.aligned.m8n8.x4.shared.b16 {%0,%1,%2,%3}, [%4];"
        : "=r"(r0), "=r"(r1), "=r"(r2), "=r"(r3) : "r"(a));
}
__device__ __forceinline__ void ldsm4t(uint32_t& r0, uint32_t& r1, uint32_t& r2, uint32_t& r3,
                                       uint32_t a) {
    asm volatile("ldmatrix.sync.aligned.m8n8.x4.trans.shared.b16 {%0,%1,%2,%3}, [%4];"
        : "=r"(r0), "=r"(r1), "=r"(r2), "=r"(r3) : "r"(a));
}
__device__ __forceinline__ void mma_f16(float& c0, float& c1, float& c2, float& c3,
                                        uint32_t a0, uint32_t a1, uint32_t a2, uint32_t a3,
                                        uint32_t b0, uint32_t b1) {
    asm volatile("mma.sync.aligned.m16n8k16.row.col.f32.f16.f16.f32 "
        "{%0,%1,%2,%3}, {%4,%5,%6,%7}, {%8,%9}, {%0,%1,%2,%3};"
        : "+f"(c0), "+f"(c1), "+f"(c2), "+f"(c3)
        : "r"(a0), "r"(a1), "r"(a2), "r"(a3), "r"(b0), "r"(b1));
}

// ============================================================
// FP16 mma.sync GEMM (round-9/16 proven config): BK=64, 2-stage cp.async.
//   MT: CTA M-tile (128 or 64); N-tile 128. 256 threads, 8 warps (2x4).
//   TRB=1: B stored [N,K]; TRB=0: B stored [K,N] via ldsm trans.
//   OUTH=1: half out (+bias)(+relu). OUTH=0: fp32 out (+bias)(+res).
// ============================================================
#define ROWH  72        // A / B-NK row pitch (64 + 8 pad halves)
#define ROWB  136       // B-KN row pitch (128 + 8 pad halves)

template<int MT, int OUTH, int TRB>
__global__ __launch_bounds__(256, MT == 64 ? 3 : 2)
void hgemm(const __half* __restrict__ A, const __half* __restrict__ B,
           void* __restrict__ Cout, const float* __restrict__ bias,
           const float* __restrict__ res, int N, int K, int relu)
{
    constexpr int MF      = MT / 32;
    constexpr int A_TILE  = MT * ROWH;
    constexpr int B_TILE  = TRB ? 128 * ROWH : 64 * ROWB;
    constexpr int STAGE_B = (A_TILE + B_TILE) * 2;

    extern __shared__ __half smh[];
    uint32_t sbase = smem_u32(smh);
    int tid  = threadIdx.x;
    int wid  = tid >> 5;
    int lane = tid & 31;
    int wm   = wid >> 2;
    int wn   = wid & 3;
    int bm = blockIdx.y * MT;
    int bn = blockIdx.x << 7;

    const __half* Ag = A + (size_t)bm * K;
    int NC = K >> 6;

    float acc[MF][4][4];
#pragma unroll
    for (int mf = 0; mf < MF; mf++)
#pragma unroll
        for (int nf = 0; nf < 4; nf++)
#pragma unroll
            for (int k = 0; k < 4; k++) acc[mf][nf][k] = 0.f;

    auto load_tile = [&](int ch, int stage) {
        int k0 = ch << 6;
        uint32_t so = sbase + (uint32_t)stage * STAGE_B;
        uint32_t bo = so + (uint32_t)A_TILE * 2u;
#pragma unroll
        for (int i = 0; i < MT / 32; i++) {
            int id = tid + (i << 8);
            int r = id >> 3, c = (id & 7) << 3;
            cpa16(so + ((uint32_t)(r * ROWH + c) << 1), Ag + (size_t)r * K + k0 + c);
        }
        if (TRB) {
            const __half* Bg = B + (size_t)bn * K;
#pragma unroll
            for (int i = 0; i < 4; i++) {
                int id = tid + (i << 8);
                int r = id >> 3, c = (id & 7) << 3;
                cpa16(bo + ((uint32_t)(r * ROWH + c) << 1), Bg + (size_t)r * K + k0 + c);
            }
        } else {
#pragma unroll
            for (int i = 0; i < 4; i++) {
                int id = tid + (i << 8);
                int r = id >> 4, c = (id & 15) << 3;
                cpa16(bo + ((uint32_t)(r * ROWB + c) << 1),
                      B + (size_t)(k0 + r) * N + bn + c);
            }
        }
    };

    load_tile(0, 0);
    asm volatile("cp.async.commit_group;");

    uint32_t rA = (uint32_t)(wm * (MT / 2)) + (lane & 7) + (((lane >> 3) & 1) << 3);
    uint32_t kA = ((lane >> 4) & 1) << 3;
    uint32_t rB = (uint32_t)(wn << 5) + (lane & 7) + (((lane >> 4) & 1) << 3);
    uint32_t kB = ((lane >> 3) & 1) << 3;
    uint32_t rBt = (lane & 7) + (((lane >> 3) & 1) << 3);
    uint32_t cBt = (uint32_t)(wn << 5) + (((lane >> 4) & 1) << 3);

    for (int ch = 0; ch < NC; ch++) {
        if (ch > 0) __syncthreads();
        if (ch + 1 < NC) load_tile(ch + 1, (ch + 1) & 1);
        asm volatile("cp.async.commit_group;");
        asm volatile("cp.async.wait_group 1;");
        __syncthreads();

        uint32_t sA = sbase + (uint32_t)(ch & 1) * STAGE_B;
        uint32_t sB = sA + (uint32_t)A_TILE * 2u;
#pragma unroll
        for (int ks = 0; ks < 4; ks++) {
            uint32_t af[MF][4], bf[4][2];
            uint32_t kofs = (uint32_t)(ks << 4);
#pragma unroll
            for (int mf = 0; mf < MF; mf++) {
                uint32_t a = sA + (((rA + (uint32_t)(mf << 4)) * ROWH + kA + kofs) << 1);
                ldsm4(af[mf][0], af[mf][1], af[mf][2], af[mf][3], a);
            }
            if (TRB) {
#pragma unroll
                for (int p = 0; p < 2; p++) {
                    uint32_t a = sB + (((rB + (uint32_t)(p << 4)) * ROWH + kB + kofs) << 1);
                    ldsm4(bf[2 * p][0], bf[2 * p][1], bf[2 * p + 1][0], bf[2 * p + 1][1], a);
                }
            } else {
#pragma unroll
                for (int p = 0; p < 2; p++) {
                    uint32_t a = sB + (((kofs + rBt) * ROWB + cBt + (uint32_t)(p << 4)) << 1);
                    ldsm4t(bf[2 * p][0], bf[2 * p][1], bf[2 * p + 1][0], bf[2 * p + 1][1], a);
                }
            }
#pragma unroll
            for (int mf = 0; mf < MF; mf++)
#pragma unroll
                for (int nf = 0; nf < 4; nf++)
                    mma_f16(acc[mf][nf][0], acc[mf][nf][1], acc[mf][nf][2], acc[mf][nf][3],
                            af[mf][0], af[mf][1], af[mf][2], af[mf][3],
                            bf[nf][0], bf[nf][1]);
        }
    }

    // ---- epilogue ----
    int row0 = bm + wm * (MT / 2) + (lane >> 2);
    int col0 = bn + (wn << 5) + ((lane & 3) << 1);
#pragma unroll
    for (int mf = 0; mf < MF; mf++) {
#pragma unroll
        for (int half_ = 0; half_ < 2; half_++) {
            int row = row0 + (mf << 4) + half_ * 8;
#pragma unroll
            for (int nf = 0; nf < 4; nf++) {
                float vx = acc[mf][nf][half_ * 2 + 0];
                float vy = acc[mf][nf][half_ * 2 + 1];
                int c = (nf << 3);
                if (bias) {
                    vx += bias[col0 + c];
                    vy += bias[col0 + c + 1];
                }
                if (OUTH) {
                    if (relu) { vx = fmaxf(vx, 0.f); vy = fmaxf(vy, 0.f); }
                    __half2 hv = __floats2half2_rn(vx, vy);
                    *(__half2*)((__half*)Cout + (size_t)row * N + col0 + c) = hv;
                } else {
                    if (res) {
                        const float* rp = res + (size_t)row * N + col0 + c;
                        float2 r2 = *(const float2*)rp;
                        vx += r2.x; vy += r2.y;
                    }
                    float2 v; v.x = vx; v.y = vy;
                    *(float2*)((float*)Cout + (size_t)row * N + col0 + c) = v;
                }
            }
        }
    }
}

// ---------------- embedding ----------------
__global__ void k_embed(const int* __restrict__ idx,
                        const float* __restrict__ tok,
                        const float* __restrict__ pos,
                        float* __restrict__ x)
{
    int m = blockIdx.x;
    int c = threadIdx.x * 4;
    int t = m & (T_SEQ - 1);
    int v = idx[m];
    float4 a = *(const float4*)(tok + (size_t)v * C_DIM + c);
    float4 p = *(const float4*)(pos + (size_t)t * C_DIM + c);
    a.x += p.x; a.y += p.y; a.z += p.z; a.w += p.w;
    *(float4*)(x + (size_t)m * C_DIM + c) = a;
}

// ---------------- layernorm: fp32 in -> fp16 out ----------------
__global__ void k_ln(const float* __restrict__ x,
                     const float* __restrict__ sc,
                     const float* __restrict__ bi,
                     __half* __restrict__ out)
{
    int m = blockIdx.x;
    int tid = threadIdx.x;                 // 256 threads
    int c = tid * 4;
    float4 v = *(const float4*)(x + (size_t)m * C_DIM + c);
    float s = v.x + v.y + v.z + v.w;
    float q = v.x*v.x + v.y*v.y + v.z*v.z + v.w*v.w;

    __shared__ float rs[8], rq[8];
#pragma unroll
    for (int o = 16; o > 0; o >>= 1) {
        s += __shfl_xor_sync(0xffffffffu, s, o);
        q += __shfl_xor_sync(0xffffffffu, q, o);
    }
    if ((tid & 31) == 0) { rs[tid >> 5] = s; rq[tid >> 5] = q; }
    __syncthreads();
    float sum = 0.f, sq = 0.f;
#pragma unroll
    for (int w = 0; w < 8; w++) { sum += rs[w]; sq += rq[w]; }

    float mu = sum * (1.0f / C_DIM);
    float var = sq * (1.0f / C_DIM) - mu * mu;
    float rstd = rsqrtf(var + 1e-5f);

    float4 svv = *(const float4*)(sc + c);
    float4 bvv = *(const float4*)(bi + c);
    __half2 p0 = __floats2half2_rn((v.x - mu) * rstd * svv.x + bvv.x,
                                   (v.y - mu) * rstd * svv.y + bvv.y);
    __half2 p1 = __floats2half2_rn((v.z - mu) * rstd * svv.z + bvv.z,
                                   (v.w - mu) * rstd * svv.w + bvv.w);
    uint2 st;
    st.x = *(uint32_t*)&p0;
    st.y = *(uint32_t*)&p1;
    *(uint2*)(out + (size_t)m * C_DIM + c) = st;
}

// ---------------- pack qkv weights ALL layers -> [L][3C, C] half ----------------
__global__ __launch_bounds__(256)
void k_packQKV(const float* __restrict__ Wq, const float* __restrict__ Wk,
               const float* __restrict__ Wv, __half* __restrict__ out)
{
    __shared__ float t[32][65];
    int b  = blockIdx.x;
    int l  = b / 1536;
    b -= l * 1536;
    int kb = b & 31;
    int hh = (b >> 5) & 15;
    int s  = b >> 9;
    const float* W = (s == 0) ? Wq : ((s == 1) ? Wk : Wv);
    const float* Wb = W + ((size_t)l * H_NUM + hh) * C_DIM * D_HEAD + (size_t)(kb << 5) * D_HEAD;
    int tid = threadIdx.x;
#pragma unroll
    for (int i = 0; i < 8; i++) {
        int idx = tid + (i << 8);
        int r = idx >> 6, d = idx & 63;
        t[r][d] = Wb[(size_t)r * D_HEAD + d];
    }
    __syncthreads();
    __half* outl = out + (size_t)l * 3 * C_DIM * C_DIM;
    int n0 = s * 1024 + hh * 64;
#pragma unroll
    for (int i = 0; i < 8; i++) {
        int idx = tid + (i << 8);
        int d = idx >> 5, kk = idx & 31;
        outl[(size_t)(n0 + d) * C_DIM + (kb << 5) + kk] = __float2half_rn(t[kk][d]);
    }
}

// ---------------- all fp32 -> fp16 converts in ONE kernel ----------------
// block ranges (2048 elems/block): tok 16000 | Wo 4096 | W1 16384 | W2 16384
#define CVT_TOK_B 16000
#define CVT_WO_B  4096
#define CVT_W1_B  16384
#define CVT_W2_B  16384
#define CVT_ALL_B (CVT_TOK_B + CVT_WO_B + CVT_W1_B + CVT_W2_B)   // 52864

__global__ __launch_bounds__(256)
void k_cvtAll(const float* __restrict__ tok, const float* __restrict__ Wo,
              const float* __restrict__ W1, const float* __restrict__ W2,
              __half* __restrict__ tokh, __half* __restrict__ woh,
              __half* __restrict__ w1h, __half* __restrict__ w2h)
{
    int bx = blockIdx.x;
    const float* src;
    __half* dst;
    size_t base;
    if (bx < CVT_TOK_B) {
        src = tok; dst = tokh; base = (size_t)bx * 2048;
    } else if (bx < CVT_TOK_B + CVT_WO_B) {
        src = Wo; dst = woh; base = (size_t)(bx - CVT_TOK_B) * 2048;
    } else if (bx < CVT_TOK_B + CVT_WO_B + CVT_W1_B) {
        src = W1; dst = w1h; base = (size_t)(bx - CVT_TOK_B - CVT_WO_B) * 2048;
    } else {
        src = W2; dst = w2h; base = (size_t)(bx - CVT_TOK_B - CVT_WO_B - CVT_W1_B) * 2048;
    }
    size_t i = base + (size_t)threadIdx.x * 8;
    float4 a = *(const float4*)(src + i);
    float4 b = *(const float4*)(src + i + 4);
    __half2 h0 = __floats2half2_rn(a.x, a.y);
    __half2 h1 = __floats2half2_rn(a.z, a.w);
    __half2 h2 = __floats2half2_rn(b.x, b.y);
    __half2 h3 = __floats2half2_rn(b.z, b.w);
    uint4 st;
    st.x = *(uint32_t*)&h0; st.y = *(uint32_t*)&h1;
    st.z = *(uint32_t*)&h2; st.w = *(uint32_t*)&h3;
    *(uint4*)(dst + i) = st;
}

// ============================================================
// Tensor-core causal flash attention — INTERLEAVED balanced pairing.
// grid (8, 32): CTA owns query tiles qlo=qtp and qhi=15-qtp in ONE K-loop:
// hi tile active every kt, lo tile while kt<=qlo. K/V loaded once per kt.
// ============================================================
#define AT_PAD  72
#define AT_TILEB (64 * AT_PAD * 2)

// one attention step on the current K/V tile for one query-tile context
#define ATTN_STEP(QF, OA, M0, M1, L0, L1, QT) do {                              \
    float s_[8][4];                                                             \
    _Pragma("unroll")                                                           \
    for (int i_ = 0; i_ < 8; i_++) { s_[i_][0]=s_[i_][1]=s_[i_][2]=s_[i_][3]=0.f; } \
    _Pragma("unroll")                                                           \
    for (int kc_ = 0; kc_ < 4; kc_++) {                                         \
        _Pragma("unroll")                                                       \
        for (int p_ = 0; p_ < 4; p_++) {                                        \
            uint32_t b0_, b1_, b2_, b3_;                                        \
            ldsm4(b0_, b1_, b2_, b3_,                                           \
                  sKt + (((rBk + (uint32_t)(p_ << 4)) * AT_PAD + kBo + (kc_ << 4)) << 1)); \
            mma_f16(s_[2*p_][0], s_[2*p_][1], s_[2*p_][2], s_[2*p_][3],         \
                    QF[kc_][0], QF[kc_][1], QF[kc_][2], QF[kc_][3], b0_, b1_);  \
            mma_f16(s_[2*p_+1][0], s_[2*p_+1][1], s_[2*p_+1][2], s_[2*p_+1][3], \
                    QF[kc_][0], QF[kc_][1], QF[kc_][2], QF[kc_][3], b2_, b3_);  \
        }                                                                       \
    }                                                                           \
    _Pragma("unroll")                                                           \
    for (int i_ = 0; i_ < 8; i_++) {                                            \
        s_[i_][0] *= 0.125f; s_[i_][1] *= 0.125f;                               \
        s_[i_][2] *= 0.125f; s_[i_][3] *= 0.125f;                               \
    }                                                                           \
    if (kt == (QT)) {                                                           \
        int r0_ = (wid << 4) + (lane >> 2);                                     \
        _Pragma("unroll")                                                       \
        for (int nf_ = 0; nf_ < 8; nf_++) {                                     \
            int c0_ = (nf_ << 3) + ((lane & 3) << 1);                           \
            if (c0_     > r0_)     s_[nf_][0] = -1e30f;                         \
            if (c0_ + 1 > r0_)     s_[nf_][1] = -1e30f;                         \
            if (c0_     > r0_ + 8) s_[nf_][2] = -1e30f;                         \
            if (c0_ + 1 > r0_ + 8) s_[nf_][3] = -1e30f;                         \
        }                                                                       \
    }                                                                           \
    float mx0_ = s_[0][0], mx1_ = s_[0][2];                                     \
    _Pragma("unroll")                                                           \
    for (int nf_ = 0; nf_ < 8; nf_++) {                                         \
        mx0_ = fmaxf(mx0_, fmaxf(s_[nf_][0], s_[nf_][1]));                      \
        mx1_ = fmaxf(mx1_, fmaxf(s_[nf_][2], s_[nf_][3]));                      \
    }                                                                           \
    mx0_ = fmaxf(mx0_, __shfl_xor_sync(0xffffffffu, mx0_, 1));                  \
    mx0_ = fmaxf(mx0_, __shfl_xor_sync(0xffffffffu, mx0_, 2));                  \
    mx1_ = fmaxf(mx1_, __shfl_xor_sync(0xffffffffu, mx1_, 1));                  \
    mx1_ = fmaxf(mx1_, __shfl_xor_sync(0xffffffffu, mx1_, 2));                  \
    float mn0_ = fmaxf(M0, mx0_), mn1_ = fmaxf(M1, mx1_);                       \
    float cr0_ = __expf(M0 - mn0_), cr1_ = __expf(M1 - mn1_);                   \
    float rs0_ = 0.f, rs1_ = 0.f;                                               \
    uint32_t pa_[4][4];                                                         \
    _Pragma("unroll")                                                           \
    for (int nf_ = 0; nf_ < 8; nf_++) {                                         \
        float p0_ = __expf(s_[nf_][0] - mn0_);                                  \
        float p1_ = __expf(s_[nf_][1] - mn0_);                                  \
        float p2_ = __expf(s_[nf_][2] - mn1_);                                  \
        float p3_ = __expf(s_[nf_][3] - mn1_);                                  \
        rs0_ += p0_ + p1_; rs1_ += p2_ + p3_;                                   \
        __half2 h01_ = __floats2half2_rn(p0_, p1_);                             \
        __half2 h23_ = __floats2half2_rn(p2_, p3_);                             \
        int kc_ = nf_ >> 1, hi_ = (nf_ & 1) << 1;                               \
        pa_[kc_][hi_]     = *(uint32_t*)&h01_;                                  \
        pa_[kc_][hi_ + 1] = *(uint32_t*)&h23_;                                  \
    }                                                                           \
    rs0_ += __shfl_xor_sync(0xffffffffu, rs0_, 1);                              \
    rs0_ += __shfl_xor_sync(0xffffffffu, rs0_, 2);                              \
    rs1_ += __shfl_xor_sync(0xffffffffu, rs1_, 1);                              \
    rs1_ += __shfl_xor_sync(0xffffffffu, rs1_, 2);                              \
    L0 = L0 * cr0_ + rs0_; L1 = L1 * cr1_ + rs1_;                               \
    M0 = mn0_; M1 = mn1_;                                                       \
    _Pragma("unroll")                                                           \
    for (int i_ = 0; i_ < 8; i_++) {                                            \
        OA[i_][0] *= cr0_; OA[i_][1] *= cr0_;                                   \
        OA[i_][2] *= cr1_; OA[i_][3] *= cr1_;                                   \
    }                                                                           \
    _Pragma("unroll")                                                           \
    for (int kc_ = 0; kc_ < 4; kc_++) {                                         \
        _Pragma("unroll")                                                       \
        for (int p_ = 0; p_ < 4; p_++) {                                        \
            uint32_t b0_, b1_, b2_, b3_;                                        \
            ldsm4t(b0_, b1_, b2_, b3_,                                          \
                   sVt + ((((uint32_t)(kc_ << 4) + rV) * AT_PAD + (uint32_t)(p_ << 4) + cV) << 1)); \
            mma_f16(OA[2*p_][0], OA[2*p_][1], OA[2*p_][2], OA[2*p_][3],         \
                    pa_[kc_][0], pa_[kc_][1], pa_[kc_][2], pa_[kc_][3], b0_, b1_); \
            mma_f16(OA[2*p_+1][0], OA[2*p_+1][1], OA[2*p_+1][2], OA[2*p_+1][3], \
                    pa_[kc_][0], pa_[kc_][1], pa_[kc_][2], pa_[kc_][3], b2_, b3_); \
        }                                                                       \
    }                                                                           \
} while (0)

__global__ __launch_bounds__(128)
void k_attn(const __half* __restrict__ qkvh, __half* __restrict__ outb)
{
    __shared__ __half QsL[64][AT_PAD];
    __shared__ __half QsH[64][AT_PAD];
    __shared__ __half Ks[2][64][AT_PAD];
    __shared__ __half Vs[2][64][AT_PAD];

    int qtp = blockIdx.x;           // 0..7
    int qlo = qtp;
    int qhi = 15 - qtp;
    int b   = blockIdx.y >> 4;
    int hh  = blockIdx.y & 15;
    int tid = threadIdx.x;
    int wid = tid >> 5, lane = tid & 31;

    const __half* qpl = qkvh + ((size_t)(b * T_SEQ + qlo * 64)) * 3072 + hh * 64;
    const __half* qph = qkvh + ((size_t)(b * T_SEQ + qhi * 64)) * 3072 + hh * 64;
    const __half* kp  = qkvh + ((size_t)(b * T_SEQ)) * 3072 + 1024 + hh * 64;
    const __half* vp  = kp + 1024;

    uint32_t sQL = smem_u32(QsL);
    uint32_t sQH = smem_u32(QsH);
    uint32_t sK  = smem_u32(Ks);
    uint32_t sV  = smem_u32(Vs);

    // prologue: both Q tiles + K0 + V0
#pragma unroll
    for (int i = 0; i < 4; i++) {
        int id = tid + (i << 7);
        int r = id >> 3, c = (id & 7) << 3;
        uint32_t off = (uint32_t)(r * AT_PAD + c) << 1;
        cpa16(sQL + off, qpl + (size_t)r * 3072 + c);
        cpa16(sQH + off, qph + (size_t)r * 3072 + c);
        cpa16(sK  + off, kp  + (size_t)r * 3072 + c);
        cpa16(sV  + off, vp  + (size_t)r * 3072 + c);
    }
    asm volatile("cp.async.commit_group;");

    uint32_t qfL[4][4], qfH[4][4];
    float oaL[8][4], oaH[8][4];
    float mL0 = -1e30f, mL1 = -1e30f, lL0 = 0.f, lL1 = 0.f;
    float mH0 = -1e30f, mH1 = -1e30f, lH0 = 0.f, lH1 = 0.f;
#pragma unroll
    for (int i = 0; i < 8; i++) {
        oaL[i][0] = oaL[i][1] = oaL[i][2] = oaL[i][3] = 0.f;
        oaH[i][0] = oaH[i][1] = oaH[i][2] = oaH[i][3] = 0.f;
    }

    uint32_t rBk = (lane & 7) + (((lane >> 4) & 1) << 3);
    uint32_t kBo = ((lane >> 3) & 1) << 3;
    uint32_t rV  = (lane & 7) + (((lane >> 3) & 1) << 3);
    uint32_t cV  = ((lane >> 4) & 1) << 3;

    for (int kt = 0; kt <= qhi; kt++) {
        if (kt > 0) __syncthreads();
        if (kt < qhi) {
            uint32_t st = (uint32_t)((kt + 1) & 1) * AT_TILEB;
#pragma unroll
            for (int i = 0; i < 4; i++) {
                int id = tid + (i << 7);
                int r = id >> 3, c = (id & 7) << 3;
                uint32_t off = (uint32_t)(r * AT_PAD + c) << 1;
                cpa16(sK + st + off, kp + (size_t)((kt + 1) * 64 + r) * 3072 + c);
                cpa16(sV + st + off, vp + (size_t)((kt + 1) * 64 + r) * 3072 + c);
            }
        }
        asm volatile("cp.async.commit_group;");
        asm volatile("cp.async.wait_group 1;");
        __syncthreads();

        if (kt == 0) {   // load both Q fragment sets once
            uint32_t rAq = (uint32_t)(wid << 4) + (lane & 7) + (((lane >> 3) & 1) << 3);
#pragma unroll
            for (int kc = 0; kc < 4; kc++) {
                uint32_t kAq = (((lane >> 4) & 1) << 3) + (kc << 4);
                ldsm4(qfL[kc][0], qfL[kc][1], qfL[kc][2], qfL[kc][3],
                      sQL + ((rAq * AT_PAD + kAq) << 1));
                ldsm4(qfH[kc][0], qfH[kc][1], qfH[kc][2], qfH[kc][3],
                      sQH + ((rAq * AT_PAD + kAq) << 1));
            }
        }

        uint32_t sKt = sK + (uint32_t)(kt & 1) * AT_TILEB;
        uint32_t sVt = sV + (uint32_t)(kt & 1) * AT_TILEB;

        // hi tile: active every iteration
        ATTN_STEP(qfH, oaH, mH0, mH1, lH0, lH1, qhi);
        // lo tile: active while kt <= qlo
        if (kt <= qlo) {
            ATTN_STEP(qfL, oaL, mL0, mL1, lL0, lL1, qlo);
        }
    }

    // ---- epilogues ----
    __half* ob = outb + (size_t)(b * T_SEQ) * C_DIM + hh * 64;
    {
        float i0 = 1.0f / lL0, i1 = 1.0f / lL1;
        int r0 = qlo * 64 + (wid << 4) + (lane >> 2);
#pragma unroll
        for (int nf = 0; nf < 8; nf++) {
            int c = (nf << 3) + ((lane & 3) << 1);
            __half2 h0 = __floats2half2_rn(oaL[nf][0] * i0, oaL[nf][1] * i0);
            __half2 h1 = __floats2half2_rn(oaL[nf][2] * i1, oaL[nf][3] * i1);
            *(__half2*)(ob + (size_t)r0 * C_DIM + c)       = h0;
            *(__half2*)(ob + (size_t)(r0 + 8) * C_DIM + c) = h1;
        }
    }
    {
        float i0 = 1.0f / lH0, i1 = 1.0f / lH1;
        int r0 = qhi * 64 + (wid << 4) + (lane >> 2);
#pragma unroll
        for (int nf = 0; nf < 8; nf++) {
            int c = (nf << 3) + ((lane & 3) << 1);
            __half2 h0 = __floats2half2_rn(oaH[nf][0] * i0, oaH[nf][1] * i0);
            __half2 h1 = __floats2half2_rn(oaH[nf][2] * i1, oaH[nf][3] * i1);
            *(__half2*)(ob + (size_t)r0 * C_DIM + c)       = h0;
            *(__half2*)(ob + (size_t)(r0 + 8) * C_DIM + c) = h1;
        }
    }
}

// ---------------- smem sizes per instantiation (BK=64, 2-stage) ----------------
#define GSM_128_NK  ((128 * ROWH + 128 * ROWH) * 2 * 2)   // 73728
#define GSM_128_KN  ((128 * ROWH + 64 * ROWB) * 2 * 2)    // 71680
#define GSM_64_KN   ((64 * ROWH + 64 * ROWB) * 2 * 2)     // 53248

// ---------------- launcher ----------------
extern "C" void kernel_launch(void* const* d_in, const int* in_sizes, int n_in,
                              void* d_out, int out_size)
{
    const int*   idx    = (const int*)  d_in[0];
    const float* tok    = (const float*)d_in[1];
    const float* pos    = (const float*)d_in[2];
    const float* ln1_s  = (const float*)d_in[3];
    const float* ln1_b  = (const float*)d_in[4];
    const float* Wq     = (const float*)d_in[5];
    const float* Wk     = (const float*)d_in[6];
    const float* Wv     = (const float*)d_in[7];
    const float* Wo     = (const float*)d_in[8];
    const float* bo     = (const float*)d_in[9];
    const float* ln2_s  = (const float*)d_in[10];
    const float* ln2_b  = (const float*)d_in[11];
    const float* W1     = (const float*)d_in[12];
    const float* b1     = (const float*)d_in[13];
    const float* W2     = (const float*)d_in[14];
    const float* b2     = (const float*)d_in[15];
    const float* lnf_s  = (const float*)d_in[16];
    const float* lnf_b  = (const float*)d_in[17];
    float* out = (float*)d_out;

    float *x;
    __half *qkvh, *hh, *ffh, *wph, *woh, *w1h, *w2h, *tokh;
    cudaGetSymbolAddress((void**)&x,     g_x);
    cudaGetSymbolAddress((void**)&qkvh,  g_qkvh);
    cudaGetSymbolAddress((void**)&hh,    g_hh);
    cudaGetSymbolAddress((void**)&ffh,   g_ffh);
    cudaGetSymbolAddress((void**)&wph,   g_wph);
    cudaGetSymbolAddress((void**)&woh,   g_woh);
    cudaGetSymbolAddress((void**)&w1h,   g_w1h);
    cudaGetSymbolAddress((void**)&w2h,   g_w2h);
    cudaGetSymbolAddress((void**)&tokh,  g_tokh);

    cudaFuncSetAttribute(hgemm<128,1,1>, cudaFuncAttributeMaxDynamicSharedMemorySize, GSM_128_NK);
    cudaFuncSetAttribute(hgemm<128,0,1>, cudaFuncAttributeMaxDynamicSharedMemorySize, GSM_128_NK);
    cudaFuncSetAttribute(hgemm<128,1,0>, cudaFuncAttributeMaxDynamicSharedMemorySize, GSM_128_KN);
    cudaFuncSetAttribute(hgemm<64,0,0>,  cudaFuncAttributeMaxDynamicSharedMemorySize, GSM_64_KN);

    // ---- one-time per call: all weight conversions (single kernel) + pack ----
    k_cvtAll<<<CVT_ALL_B, 256>>>(tok, Wo, W1, W2, tokh, woh, w1h, w2h);
    k_packQKV<<<L_NUM * 1536, 256>>>(Wq, Wk, Wv, wph);
    k_embed<<<M_ROWS, 256>>>(idx, tok, pos, x);

    for (int l = 0; l < L_NUM; l++) {
        // LN1 -> half
        k_ln<<<M_ROWS, 256>>>(x, ln1_s + l * C_DIM, ln1_b + l * C_DIM, hh);
        // qkv = hh @ wph^T -> half  (MT=128)
        hgemm<128,1,1><<<dim3(3072 / 128, M_ROWS / 128), 256, GSM_128_NK>>>(
            hh, wph + (size_t)l * 3 * C_DIM * C_DIM, qkvh, nullptr, nullptr, 3072, C_DIM, 0);
        // interleaved balanced flash attention -> hh
        k_attn<<<dim3(T_SEQ / 128, B_SZ * H_NUM), 128>>>(qkvh, hh);
        // x = x + hh @ Wo + bo   (Wo [K,N], MT=64)
        hgemm<64,0,0><<<dim3(C_DIM / 128, M_ROWS / 64), 256, GSM_64_KN>>>(
            hh, woh + (size_t)l * C_DIM * C_DIM, x, bo + l * C_DIM, x, C_DIM, C_DIM, 0);
        // LN2 -> half
        k_ln<<<M_ROWS, 256>>>(x, ln2_s + l * C_DIM, ln2_b + l * C_DIM, hh);
        // ffh = relu(hh @ W1 + b1) -> half  (W1 [K,N], MT=128)
        hgemm<128,1,0><<<dim3(FF_DIM / 128, M_ROWS / 128), 256, GSM_128_KN>>>(
            hh, w1h + (size_t)l * C_DIM * FF_DIM, ffh, b1 + l * FF_DIM, nullptr, FF_DIM, C_DIM, 1);
        // x = x + ffh @ W2 + b2  (W2 [K,N], MT=64)
        hgemm<64,0,0><<<dim3(C_DIM / 128, M_ROWS / 64), 256, GSM_64_KN>>>(
            ffh, w2h + (size_t)l * FF_DIM * C_DIM, x, b2 + l * C_DIM, x, C_DIM, FF_DIM, 0);
    }

    // final LN + tied-embedding logits (tok [V,K] -> MT=128 TRB=1)
    k_ln<<<M_ROWS, 256>>>(x, lnf_s, lnf_b, hh);
    hgemm<128,0,1><<<dim3(V_SZ / 128, M_ROWS / 128), 256, GSM_128_NK>>>(
        hh, tokh, out, nullptr, nullptr, V_SZ, C_DIM, 0);
}